// round 5
// baseline (speedup 1.0000x reference)
#include <cuda_runtime.h>
#include <math.h>

// ---------------- problem constants ----------------
#define B_  32
#define T_  256
#define D_  512
#define NH_ 8
#define DK_ 64
#define L_  2
#define ML_ 25
#define NWMAT 13

// ---------------- scratch ----------------
__device__ float g_enc[B_*T_*D_];
__device__ float g_tmp[B_*T_*D_];
__device__ float g_q  [B_*T_*D_];
__device__ float g_k  [B_*T_*D_];
__device__ float g_v  [B_*T_*D_];
__device__ float g_o  [B_*T_*D_];
__device__ float g_p  [B_*NH_*T_*T_];
__device__ float g_wT [NWMAT*D_*D_];

__device__ __forceinline__ unsigned f2tf32(float x) {
    unsigned r;
    asm("cvt.rna.tf32.f32 %0, %1;" : "=r"(r) : "f"(x));
    return r;
}
__device__ __forceinline__ float rndtf(float v) { return __uint_as_float(f2tf32(v)); }
__device__ __forceinline__ float tanh_fast(float x) {
    float y;
    asm("tanh.approx.f32 %0, %1;" : "=f"(y) : "f"(x));
    return y;
}
__device__ __forceinline__ void st_perm(float* rowp, int c, float v) {
    rowp[(c & ~31) + (c & 3) * 8 + ((c & 31) >> 2)] = rndtf(v);
}

#define CP16(dst, src) \
    asm volatile("cp.async.cg.shared.global [%0], [%1], 16;" :: "r"(dst), "l"(src) : "memory")

__device__ __forceinline__ void mma_tf32(float c[4],
                                         float a0, float a1, float a2, float a3,
                                         float b0, float b1)
{
    asm volatile(
        "mma.sync.aligned.m16n8k8.row.col.f32.tf32.tf32.f32 "
        "{%0,%1,%2,%3}, {%4,%5,%6,%7}, {%8,%9}, {%0,%1,%2,%3};"
        : "+f"(c[0]), "+f"(c[1]), "+f"(c[2]), "+f"(c[3])
        : "r"(__float_as_uint(a0)), "r"(__float_as_uint(a1)),
          "r"(__float_as_uint(a2)), "r"(__float_as_uint(a3)),
          "r"(__float_as_uint(b0)), "r"(__float_as_uint(b1)));
}

// ---------------- prep ----------------
__global__ void prep_kernel(const float* __restrict__ x, const float* __restrict__ pos,
                            const int* __restrict__ ewp, float* __restrict__ enc)
{
    __shared__ float tile[32][33];
    int b  = blockIdx.z;
    int d0 = blockIdx.x * 32, t0 = blockIdx.y * 32;
    int tx = threadIdx.x, ty = threadIdx.y;
    const float* xb = x + (long long)b * D_ * T_;
    #pragma unroll
    for (int i = 0; i < 4; i++) {
        int d = ty + i * 8;
        tile[d][tx] = xb[(long long)(d0 + d) * T_ + t0 + tx];
    }
    __syncthreads();
    #pragma unroll
    for (int i = 0; i < 4; i++) {
        int tl = ty + i * 8;
        int t = t0 + tl, d = d0 + tx;
        int pr = ewp[t];
        enc[(((long long)b * T_) + t) * D_ + d] =
            tile[tx][tl] * 22.62741699796952f + pos[(long long)pr * D_ + d];
    }
}

// ---------------- weight transpose (perm+round) ----------------
struct WP { const float* w[NWMAT]; };
__global__ void wtrans_kernel(WP p, float* __restrict__ out)
{
    __shared__ float t[32][33];
    int mi = blockIdx.z;
    const float* W = p.w[mi];
    float* O = out + (long long)mi * D_ * D_;
    int n0 = blockIdx.x * 32, k0 = blockIdx.y * 32;
    int tx = threadIdx.x, ty = threadIdx.y;
    #pragma unroll
    for (int i = 0; i < 4; i++) {
        int k = k0 + ty + i * 8;
        t[ty + i * 8][tx] = W[(long long)k * D_ + n0 + tx];
    }
    __syncthreads();
    #pragma unroll
    for (int i = 0; i < 4; i++) {
        int n = n0 + ty + i * 8;
        O[(long long)n * D_ + k0 + (tx & 3) * 8 + (tx >> 2)] = rndtf(t[tx][ty + i * 8]);
    }
}

// ---------------- layernorm (perm+round output) ----------------
__global__ void ln_kernel(const float* __restrict__ in, float* __restrict__ out,
                          const float* __restrict__ gs, const float* __restrict__ gb)
{
    int row  = blockIdx.x * 8 + threadIdx.y;
    int lane = threadIdx.x;
    const float* r = in + (long long)row * D_;
    float4 xv[4];
    #pragma unroll
    for (int j = 0; j < 4; j++)
        xv[j] = *reinterpret_cast<const float4*>(&r[(j * 32 + lane) * 4]);
    float s = 0.f;
    #pragma unroll
    for (int j = 0; j < 4; j++) s += xv[j].x + xv[j].y + xv[j].z + xv[j].w;
    #pragma unroll
    for (int o = 16; o; o >>= 1) s += __shfl_xor_sync(0xffffffffu, s, o);
    float mean = s * (1.0f / D_);
    float vs = 0.f;
    #pragma unroll
    for (int j = 0; j < 4; j++) {
        float a = xv[j].x - mean, b2 = xv[j].y - mean, c = xv[j].z - mean, d = xv[j].w - mean;
        vs += a * a + b2 * b2 + c * c + d * d;
    }
    #pragma unroll
    for (int o = 16; o; o >>= 1) vs += __shfl_xor_sync(0xffffffffu, vs, o);
    float rstd = rsqrtf(vs * (1.0f / D_) + 1e-5f);
    float* w = out + (long long)row * D_;
    #pragma unroll
    for (int j = 0; j < 4; j++) {
        int c0 = (j * 32 + lane) * 4;
        float4 sv = *reinterpret_cast<const float4*>(&gs[c0]);
        float4 bv = *reinterpret_cast<const float4*>(&gb[c0]);
        float tx = (xv[j].x - mean) * rstd * sv.x + bv.x;
        float ty = (xv[j].y - mean) * rstd * sv.y + bv.y;
        float tz = (xv[j].z - mean) * rstd * sv.z + bv.z;
        float tw = (xv[j].w - mean) * rstd * sv.w + bv.w;
        float* wp = w + (c0 & ~31);
        int qq = (c0 & 31) >> 2;
        wp[qq]      = rndtf(tx);
        wp[8 + qq]  = rndtf(ty);
        wp[16 + qq] = rndtf(tz);
        wp[24 + qq] = rndtf(tw);
    }
}

// ---------------- softmax over rows of 256 ----------------
__global__ void softmax_kernel(float* __restrict__ P)
{
    long long row = (long long)blockIdx.x * 8 + threadIdx.y;
    float* r = P + row * T_;
    int lane = threadIdx.x;
    float4 a = *reinterpret_cast<const float4*>(&r[lane * 4]);
    float4 b = *reinterpret_cast<const float4*>(&r[128 + lane * 4]);
    float m = fmaxf(fmaxf(fmaxf(a.x, a.y), fmaxf(a.z, a.w)),
                    fmaxf(fmaxf(b.x, b.y), fmaxf(b.z, b.w)));
    #pragma unroll
    for (int o = 16; o; o >>= 1) m = fmaxf(m, __shfl_xor_sync(0xffffffffu, m, o));
    a.x = __expf(a.x - m); a.y = __expf(a.y - m); a.z = __expf(a.z - m); a.w = __expf(a.w - m);
    b.x = __expf(b.x - m); b.y = __expf(b.y - m); b.z = __expf(b.z - m); b.w = __expf(b.w - m);
    float s = a.x + a.y + a.z + a.w + b.x + b.y + b.z + b.w;
    #pragma unroll
    for (int o = 16; o; o >>= 1) s += __shfl_xor_sync(0xffffffffu, s, o);
    float inv = 1.0f / s;
    a.x *= inv; a.y *= inv; a.z *= inv; a.w *= inv;
    b.x *= inv; b.y *= inv; b.z *= inv; b.w *= inv;
    *reinterpret_cast<float4*>(&r[lane * 4]) = a;
    *reinterpret_cast<float4*>(&r[128 + lane * 4]) = b;
}

// ======================================================================
// 128x128 tf32 MMA GEMM, 3-stage cp.async. grid.z selects output set.
// C = A[8192,512] @ Bt[512,512]^T (+bias)(+relu)(+resid)
// flags: bit0 relu, bit1 perm+round output.
// ======================================================================
#define QBK 32
#define QSTR 36
#define QASTG (128 * QSTR)
#define QSTAGES 3
#define QNKT (D_ / QBK)
#define TG_SMEM (QSTAGES * 2 * QASTG * 4)   // 110592 B

struct TGB { const float* Bt; float* C; const float* bias; const float* resid; int flags; };
struct TGArgs { TGB t[3]; };

__global__ void __launch_bounds__(256) tgemm_kernel(const float* __restrict__ A, TGArgs args)
{
    extern __shared__ float sm[];
    float* sA = sm;
    float* sB = sm + QSTAGES * QASTG;

    TGB tb = args.t[blockIdx.z];
    int tid = threadIdx.x, w = tid >> 5, lane = tid & 31;
    int g = lane >> 2, tig = lane & 3;
    int bm = blockIdx.y * 128, bn = blockIdx.x * 128;
    int wm = (w >> 2) * 64, wn = (w & 3) * 32;

    unsigned uA = (unsigned)__cvta_generic_to_shared(sA);
    unsigned uB = (unsigned)__cvta_generic_to_shared(sB);
    int crow = tid >> 3, cc4 = tid & 7;

    const float* aP[4]; const float* bP[4];
    unsigned dA[4], dB[4];
    #pragma unroll
    for (int i = 0; i < 4; i++) {
        aP[i] = A      + (long long)(bm + crow + i * 32) * D_ + cc4 * 4;
        bP[i] = tb.Bt  + (long long)(bn + crow + i * 32) * D_ + cc4 * 4;
        dA[i] = uA + (unsigned)(((crow + i * 32) * QSTR + cc4 * 4) * 4);
        dB[i] = uB + (unsigned)(((crow + i * 32) * QSTR + cc4 * 4) * 4);
    }

    float acc[4][4][4];
    #pragma unroll
    for (int i = 0; i < 4; i++)
        #pragma unroll
        for (int j = 0; j < 4; j++)
            #pragma unroll
            for (int q = 0; q < 4; q++) acc[i][j][q] = 0.f;

    #pragma unroll
    for (int s = 0; s < QSTAGES; s++) {
        #pragma unroll
        for (int i = 0; i < 4; i++) {
            CP16(dA[i] + (unsigned)(s * QASTG * 4), aP[i] + s * QBK);
            CP16(dB[i] + (unsigned)(s * QASTG * 4), bP[i] + s * QBK);
        }
        asm volatile("cp.async.commit_group;" ::: "memory");
    }

    for (int kt = 0; kt < QNKT; kt++) {
        asm volatile("cp.async.wait_group 2;" ::: "memory");
        __syncthreads();
        int s = kt % QSTAGES;
        const float* pA = sA + s * QASTG;
        const float* pB = sB + s * QASTG;

        float aF[8][8], bF[4][8];
        #pragma unroll
        for (int r = 0; r < 8; r++) {
            const float* rp = pA + (wm + r * 8 + g) * QSTR + tig * 8;
            *reinterpret_cast<float4*>(&aF[r][0]) = *reinterpret_cast<const float4*>(rp);
            *reinterpret_cast<float4*>(&aF[r][4]) = *reinterpret_cast<const float4*>(rp + 4);
        }
        #pragma unroll
        for (int r = 0; r < 4; r++) {
            const float* rp = pB + (wn + r * 8 + g) * QSTR + tig * 8;
            *reinterpret_cast<float4*>(&bF[r][0]) = *reinterpret_cast<const float4*>(rp);
            *reinterpret_cast<float4*>(&bF[r][4]) = *reinterpret_cast<const float4*>(rp + 4);
        }
        __syncthreads();

        if (kt + QSTAGES < QNKT) {
            int ko = (kt + QSTAGES) * QBK;
            #pragma unroll
            for (int i = 0; i < 4; i++) {
                CP16(dA[i] + (unsigned)(s * QASTG * 4), aP[i] + ko);
                CP16(dB[i] + (unsigned)(s * QASTG * 4), bP[i] + ko);
            }
        }
        asm volatile("cp.async.commit_group;" ::: "memory");

        #pragma unroll
        for (int ks = 0; ks < 4; ks++)
            #pragma unroll
            for (int mt = 0; mt < 4; mt++)
                #pragma unroll
                for (int nt = 0; nt < 4; nt++)
                    mma_tf32(acc[mt][nt],
                             aF[2 * mt][2 * ks], aF[2 * mt + 1][2 * ks],
                             aF[2 * mt][2 * ks + 1], aF[2 * mt + 1][2 * ks + 1],
                             bF[nt][2 * ks], bF[nt][2 * ks + 1]);
    }

    int flags = tb.flags;
    #pragma unroll
    for (int mt = 0; mt < 4; mt++) {
        #pragma unroll
        for (int nt = 0; nt < 4; nt++) {
            int row0 = bm + wm + mt * 16 + g;
            int col  = bn + wn + nt * 8 + 2 * tig;
            float2 bv = *reinterpret_cast<const float2*>(&tb.bias[col]);
            float v00 = acc[mt][nt][0] + bv.x, v01 = acc[mt][nt][1] + bv.y;
            float v10 = acc[mt][nt][2] + bv.x, v11 = acc[mt][nt][3] + bv.y;
            if (flags & 1) {
                v00 = fmaxf(v00, 0.f); v01 = fmaxf(v01, 0.f);
                v10 = fmaxf(v10, 0.f); v11 = fmaxf(v11, 0.f);
            }
            if (tb.resid) {
                float2 r0 = *reinterpret_cast<const float2*>(
                    &tb.resid[(long long)row0 * D_ + col]);
                float2 r1 = *reinterpret_cast<const float2*>(
                    &tb.resid[(long long)(row0 + 8) * D_ + col]);
                v00 += r0.x; v01 += r0.y; v10 += r1.x; v11 += r1.y;
            }
            if (flags & 2) {
                float* r0p = &tb.C[(long long)row0 * D_];
                float* r1p = &tb.C[(long long)(row0 + 8) * D_];
                st_perm(r0p, col, v00); st_perm(r0p, col + 1, v01);
                st_perm(r1p, col, v10); st_perm(r1p, col + 1, v11);
            } else {
                *reinterpret_cast<float2*>(&tb.C[(long long)row0 * D_ + col]) =
                    make_float2(v00, v01);
                *reinterpret_cast<float2*>(&tb.C[(long long)(row0 + 8) * D_ + col]) =
                    make_float2(v10, v11);
            }
        }
    }
}

// ======================================================================
// QK^T tf32: per (b,h): S[256,256] = Q_h[256,64] @ K_h[256,64]^T * 0.125
// Q,K stored perm+rounded. 128x128 tile, K=64 (2 iters), 2 stages.
// ======================================================================
#define QKSTAGES 2
#define QK_SMEM (QKSTAGES * 2 * QASTG * 4)   // 73728 B

__global__ void __launch_bounds__(256) qk_kernel(
    const float* __restrict__ q, const float* __restrict__ k, float* __restrict__ P)
{
    extern __shared__ float sm[];
    float* sA = sm;
    float* sB = sm + QKSTAGES * QASTG;

    int z = blockIdx.z;
    int b = z >> 3, h = z & 7;
    const float* A  = q + (long long)b * T_ * D_ + h * DK_;
    const float* Bt = k + (long long)b * T_ * D_ + h * DK_;
    float* C = P + (long long)z * T_ * T_;

    int tid = threadIdx.x, w = tid >> 5, lane = tid & 31;
    int g = lane >> 2, tig = lane & 3;
    int bm = blockIdx.y * 128, bn = blockIdx.x * 128;
    int wm = (w >> 2) * 64, wn = (w & 3) * 32;

    unsigned uA = (unsigned)__cvta_generic_to_shared(sA);
    unsigned uB = (unsigned)__cvta_generic_to_shared(sB);
    int crow = tid >> 3, cc4 = tid & 7;

    const float* aP[4]; const float* bP[4];
    unsigned dA[4], dB[4];
    #pragma unroll
    for (int i = 0; i < 4; i++) {
        aP[i] = A  + (long long)(bm + crow + i * 32) * D_ + cc4 * 4;
        bP[i] = Bt + (long long)(bn + crow + i * 32) * D_ + cc4 * 4;
        dA[i] = uA + (unsigned)(((crow + i * 32) * QSTR + cc4 * 4) * 4);
        dB[i] = uB + (unsigned)(((crow + i * 32) * QSTR + cc4 * 4) * 4);
    }

    float acc[4][4][4];
    #pragma unroll
    for (int i = 0; i < 4; i++)
        #pragma unroll
        for (int j = 0; j < 4; j++)
            #pragma unroll
            for (int qq = 0; qq < 4; qq++) acc[i][j][qq] = 0.f;

    #pragma unroll
    for (int s = 0; s < QKSTAGES; s++) {
        #pragma unroll
        for (int i = 0; i < 4; i++) {
            CP16(dA[i] + (unsigned)(s * QASTG * 4), aP[i] + s * QBK);
            CP16(dB[i] + (unsigned)(s * QASTG * 4), bP[i] + s * QBK);
        }
        asm volatile("cp.async.commit_group;" ::: "memory");
    }

    #pragma unroll
    for (int kt = 0; kt < 2; kt++) {
        asm volatile("cp.async.wait_group 1;" ::: "memory");
        __syncthreads();
        const float* pA = sA + kt * QASTG;
        const float* pB = sB + kt * QASTG;

        float aF[8][8], bF[4][8];
        #pragma unroll
        for (int r = 0; r < 8; r++) {
            const float* rp = pA + (wm + r * 8 + g) * QSTR + tig * 8;
            *reinterpret_cast<float4*>(&aF[r][0]) = *reinterpret_cast<const float4*>(rp);
            *reinterpret_cast<float4*>(&aF[r][4]) = *reinterpret_cast<const float4*>(rp + 4);
        }
        #pragma unroll
        for (int r = 0; r < 4; r++) {
            const float* rp = pB + (wn + r * 8 + g) * QSTR + tig * 8;
            *reinterpret_cast<float4*>(&bF[r][0]) = *reinterpret_cast<const float4*>(rp);
            *reinterpret_cast<float4*>(&bF[r][4]) = *reinterpret_cast<const float4*>(rp + 4);
        }
        asm volatile("cp.async.commit_group;" ::: "memory");

        #pragma unroll
        for (int ks = 0; ks < 4; ks++)
            #pragma unroll
            for (int mt = 0; mt < 4; mt++)
                #pragma unroll
                for (int nt = 0; nt < 4; nt++)
                    mma_tf32(acc[mt][nt],
                             aF[2 * mt][2 * ks], aF[2 * mt + 1][2 * ks],
                             aF[2 * mt][2 * ks + 1], aF[2 * mt + 1][2 * ks + 1],
                             bF[nt][2 * ks], bF[nt][2 * ks + 1]);
    }

    #pragma unroll
    for (int mt = 0; mt < 4; mt++)
        #pragma unroll
        for (int nt = 0; nt < 4; nt++) {
            int row0 = bm + wm + mt * 16 + g;
            int col  = bn + wn + nt * 8 + 2 * tig;
            *reinterpret_cast<float2*>(&C[(long long)row0 * T_ + col]) =
                make_float2(acc[mt][nt][0] * 0.125f, acc[mt][nt][1] * 0.125f);
            *reinterpret_cast<float2*>(&C[(long long)(row0 + 8) * T_ + col]) =
                make_float2(acc[mt][nt][2] * 0.125f, acc[mt][nt][3] * 0.125f);
        }
}

// ---------------- scalar batched SGEMM (PV only) ----------------
#define BM 128
#define BN 64
#define BK 16

__global__ void __launch_bounds__(256) gemm_pv(
    const float* __restrict__ A, const float* __restrict__ B,
    float* __restrict__ C)
{
    __shared__ float As[BK][BM + 4];
    __shared__ float Bs[BK][BN + 4];
    int z = blockIdx.z;
    A += (long long)z * T_ * T_;
    B += (long long)(z >> 3) * T_ * D_ + (z & 7) * DK_;
    C += (long long)(z >> 3) * T_ * D_ + (z & 7) * DK_;

    int bm  = blockIdx.y * BM;
    int tid = threadIdx.x;
    int tx  = tid & 15, ty = tid >> 4;

    float acc[8][4];
    #pragma unroll
    for (int i = 0; i < 8; i++)
        #pragma unroll
        for (int j = 0; j < 4; j++) acc[i][j] = 0.f;

    for (int kt = 0; kt < T_; kt += BK) {
        __syncthreads();
        #pragma unroll
        for (int i = 0; i < 2; i++) {
            int e = i * 256 + tid;
            int row = e >> 2, c4 = e & 3;
            float4 va = *reinterpret_cast<const float4*>(
                &A[(long long)(bm + row) * T_ + kt + c4 * 4]);
            As[c4 * 4 + 0][row] = va.x;
            As[c4 * 4 + 1][row] = va.y;
            As[c4 * 4 + 2][row] = va.z;
            As[c4 * 4 + 3][row] = va.w;
        }
        {
            int r2 = tid >> 4, c4 = tid & 15;
            float4 vb = *reinterpret_cast<const float4*>(
                &B[(long long)(kt + r2) * D_ + c4 * 4]);
            *reinterpret_cast<float4*>(&Bs[r2][c4 * 4]) = vb;
        }
        __syncthreads();
        #pragma unroll
        for (int kk = 0; kk < BK; kk++) {
            float4 a0 = *reinterpret_cast<const float4*>(&As[kk][ty * 8]);
            float4 a1 = *reinterpret_cast<const float4*>(&As[kk][ty * 8 + 4]);
            float4 bv = *reinterpret_cast<const float4*>(&Bs[kk][tx * 4]);
            float av[8] = {a0.x, a0.y, a0.z, a0.w, a1.x, a1.y, a1.z, a1.w};
            float bb[4] = {bv.x, bv.y, bv.z, bv.w};
            #pragma unroll
            for (int i = 0; i < 8; i++)
                #pragma unroll
                for (int j = 0; j < 4; j++)
                    acc[i][j] += av[i] * bb[j];
        }
    }

    #pragma unroll
    for (int i = 0; i < 8; i++) {
        int row = bm + ty * 8 + i;
        int col = (blockIdx.z & 7) * DK_ + tx * 4;   // global column for perm
        float* rp = &C[(long long)row * D_ - (long long)(blockIdx.z & 7) * DK_ + (col & ~31)];
        int qq = (col & 31) >> 2;
        rp[qq]      = rndtf(acc[i][0]);
        rp[8 + qq]  = rndtf(acc[i][1]);
        rp[16 + qq] = rndtf(acc[i][2]);
        rp[24 + qq] = rndtf(acc[i][3]);
    }
}

// ---------------- PVAM head ----------------
__global__ void __launch_bounds__(256) pvam_kernel(
    const float* __restrict__ wf, const float* __restrict__ emb,
    const int* __restrict__ gwp, const float* __restrict__ fc1,
    float* __restrict__ out)
{
    __shared__ float s_wp[D_];
    __shared__ float s_f[D_];
    __shared__ float s_sc[T_];
    __shared__ float s_red[32];
    int m = blockIdx.x, b = blockIdx.y;
    int tid = threadIdx.x;
    int er = gwp[m];
    for (int i = tid; i < D_; i += 256) {
        s_wp[i] = emb[(long long)er * D_ + i];
        s_f[i]  = fc1[i];
    }
    __syncthreads();

    const float* wr = wf + ((long long)b * T_ + tid) * D_;
    float sc = 0.f;
    #pragma unroll 4
    for (int c4 = 0; c4 < D_ / 4; c4++) {
        float4 w = *reinterpret_cast<const float4*>(&wr[c4 * 4]);
        float4 p = *reinterpret_cast<const float4*>(&s_wp[c4 * 4]);
        float4 f = *reinterpret_cast<const float4*>(&s_f[c4 * 4]);
        sc += tanh_fast(w.x + p.x) * f.x;
        sc += tanh_fast(w.y + p.y) * f.y;
        sc += tanh_fast(w.z + p.z) * f.z;
        sc += tanh_fast(w.w + p.w) * f.w;
    }

    int wid = tid >> 5, lane = tid & 31;
    float mv = sc;
    #pragma unroll
    for (int o = 16; o; o >>= 1) mv = fmaxf(mv, __shfl_xor_sync(0xffffffffu, mv, o));
    if (lane == 0) s_red[wid] = mv;
    __syncthreads();
    if (tid < 32) {
        float t = (tid < 8) ? s_red[tid] : -3.0e38f;
        #pragma unroll
        for (int o = 4; o; o >>= 1) t = fmaxf(t, __shfl_xor_sync(0xffffffffu, t, o));
        if (tid == 0) s_red[8] = t;
    }
    __syncthreads();
    float bmax = s_red[8];
    float e = __expf(sc - bmax);
    float sv = e;
    #pragma unroll
    for (int o = 16; o; o >>= 1) sv += __shfl_xor_sync(0xffffffffu, sv, o);
    if (lane == 0) s_red[16 + wid] = sv;
    __syncthreads();
    if (tid < 32) {
        float t = (tid < 8) ? s_red[16 + tid] : 0.f;
        #pragma unroll
        for (int o = 4; o; o >>= 1) t += __shfl_xor_sync(0xffffffffu, t, o);
        if (tid == 0) s_red[25] = t;
    }
    __syncthreads();
    float inv = 1.0f / s_red[25];
    s_sc[tid] = e * inv;
    __syncthreads();

    long long base = (long long)b * T_ * D_;
    for (int c = tid; c < D_; c += 256) {
        float acc = 0.f;
        #pragma unroll 8
        for (int t = 0; t < T_; t++)
            acc += s_sc[t] * wf[base + (long long)t * D_ + c];
        out[(((long long)b * ML_) + m) * D_ + c] = acc;
    }
}

// ---------------- host launcher ----------------
extern "C" void kernel_launch(void* const* d_in, const int* in_sizes, int n_in,
                              void* d_out, int out_size)
{
    const float* x    = (const float*)d_in[0];
    const int*   ewp  = (const int*)  d_in[1];
    const int*   gwp  = (const int*)  d_in[2];
    const float* pos  = (const float*)d_in[3];
    const float* ln1s = (const float*)d_in[4];
    const float* ln1b = (const float*)d_in[5];
    const float* Wq   = (const float*)d_in[6];
    const float* bq   = (const float*)d_in[7];
    const float* Wk   = (const float*)d_in[8];
    const float* bk   = (const float*)d_in[9];
    const float* Wv   = (const float*)d_in[10];
    const float* bv   = (const float*)d_in[11];
    const float* Wo   = (const float*)d_in[12];
    const float* bo   = (const float*)d_in[13];
    const float* ln2s = (const float*)d_in[14];
    const float* ln2b = (const float*)d_in[15];
    const float* W1   = (const float*)d_in[16];
    const float* b1   = (const float*)d_in[17];
    const float* W2   = (const float*)d_in[18];
    const float* b2   = (const float*)d_in[19];
    const float* lnfs = (const float*)d_in[20];
    const float* lnfb = (const float*)d_in[21];
    const float* fc0w = (const float*)d_in[22];
    const float* fc0b = (const float*)d_in[23];
    const float* emb  = (const float*)d_in[24];
    const float* fc1  = (const float*)d_in[25];

    static float *enc = nullptr, *tmp, *q, *k, *v, *o, *p, *wT;
    if (!enc) {
        cudaGetSymbolAddress((void**)&enc, g_enc);
        cudaGetSymbolAddress((void**)&tmp, g_tmp);
        cudaGetSymbolAddress((void**)&q,   g_q);
        cudaGetSymbolAddress((void**)&k,   g_k);
        cudaGetSymbolAddress((void**)&v,   g_v);
        cudaGetSymbolAddress((void**)&o,   g_o);
        cudaGetSymbolAddress((void**)&p,   g_p);
        cudaGetSymbolAddress((void**)&wT,  g_wT);
        cudaFuncSetAttribute(tgemm_kernel,
                             cudaFuncAttributeMaxDynamicSharedMemorySize, TG_SMEM);
        cudaFuncSetAttribute(qk_kernel,
                             cudaFuncAttributeMaxDynamicSharedMemorySize, QK_SMEM);
    }

    const long long DD = (long long)D_ * D_;

    WP wp;
    wp.w[0]  = Wq;       wp.w[1]  = Wk;       wp.w[2]  = Wv;
    wp.w[3]  = Wo;       wp.w[4]  = W1;       wp.w[5]  = W2;
    wp.w[6]  = Wq + DD;  wp.w[7]  = Wk + DD;  wp.w[8]  = Wv + DD;
    wp.w[9]  = Wo + DD;  wp.w[10] = W1 + DD;  wp.w[11] = W2 + DD;
    wp.w[12] = fc0w;
    wtrans_kernel<<<dim3(16, 16, NWMAT), dim3(32, 8)>>>(wp, wT);

    prep_kernel<<<dim3(D_ / 32, T_ / 32, B_), dim3(32, 8)>>>(x, pos, ewp, enc);

    const int MT = B_ * T_;   // 8192
    const dim3 tg1(D_ / 128, MT / 128, 1);   // (4,64,1)
    const dim3 tg3(D_ / 128, MT / 128, 3);

    for (int l = 0; l < L_; l++) {
        int vo = l * D_;
        const float* wq = wT + (l * 6 + 0) * DD;
        const float* wk = wT + (l * 6 + 1) * DD;
        const float* wv = wT + (l * 6 + 2) * DD;
        const float* wo = wT + (l * 6 + 3) * DD;
        const float* w1 = wT + (l * 6 + 4) * DD;
        const float* w2 = wT + (l * 6 + 5) * DD;

        ln_kernel<<<MT / 8, dim3(32, 8)>>>(enc, tmp, ln1s + vo, ln1b + vo);

        TGArgs aqkv;
        aqkv.t[0] = {wq, q, bq + vo, nullptr, 2};
        aqkv.t[1] = {wk, k, bk + vo, nullptr, 2};
        aqkv.t[2] = {wv, v, bv + vo, nullptr, 0};
        tgemm_kernel<<<tg3, 256, TG_SMEM>>>(tmp, aqkv);

        qk_kernel<<<dim3(2, 2, B_ * NH_), 256, QK_SMEM>>>(q, k, p);
        softmax_kernel<<<(B_ * NH_ * T_) / 8, dim3(32, 8)>>>(p);
        gemm_pv<<<dim3(1, 2, B_ * NH_), 256>>>(p, v, o);   // o perm+rounded

        TGArgs ao; ao.t[0] = {wo, enc, bo + vo, enc, 0};
        tgemm_kernel<<<tg1, 256, TG_SMEM>>>(o, ao);

        ln_kernel<<<MT / 8, dim3(32, 8)>>>(enc, tmp, ln2s + vo, ln2b + vo);
        TGArgs a1; a1.t[0] = {w1, o, b1 + vo, nullptr, 3};
        tgemm_kernel<<<tg1, 256, TG_SMEM>>>(tmp, a1);
        TGArgs a2; a2.t[0] = {w2, enc, b2 + vo, enc, 0};
        tgemm_kernel<<<tg1, 256, TG_SMEM>>>(o, a2);
    }

    ln_kernel<<<MT / 8, dim3(32, 8)>>>(enc, tmp, lnfs, lnfb);
    TGArgs af; af.t[0] = {wT + 12 * DD, q, fc0b, nullptr, 0};
    tgemm_kernel<<<tg1, 256, TG_SMEM>>>(tmp, af);

    pvam_kernel<<<dim3(ML_, B_), 256>>>(q, emb, gwp, fc1, (float*)d_out);
}

// round 6
// speedup vs baseline: 1.2313x; 1.2313x over previous
#include <cuda_runtime.h>
#include <math.h>

// ---------------- problem constants ----------------
#define B_  32
#define T_  256
#define D_  512
#define NH_ 8
#define DK_ 64
#define L_  2
#define ML_ 25
#define NWMAT 13

// ---------------- scratch ----------------
__device__ float g_enc[B_*T_*D_];
__device__ float g_tmp[B_*T_*D_];
__device__ float g_q  [B_*T_*D_];
__device__ float g_k  [B_*T_*D_];
__device__ float g_v  [B_*T_*D_];   // holds V^T [512, 8192]
__device__ float g_o  [B_*T_*D_];
__device__ float g_p  [B_*NH_*T_*T_];
__device__ float g_wT [NWMAT*D_*D_];

__device__ __forceinline__ unsigned f2tf32(float x) {
    unsigned r;
    asm("cvt.rna.tf32.f32 %0, %1;" : "=r"(r) : "f"(x));
    return r;
}
__device__ __forceinline__ float rndtf(float v) { return __uint_as_float(f2tf32(v)); }
__device__ __forceinline__ float tanh_fast(float x) {
    float y;
    asm("tanh.approx.f32 %0, %1;" : "=f"(y) : "f"(x));
    return y;
}
__device__ __forceinline__ void st_perm(float* rowp, int c, float v) {
    rowp[(c & ~31) + (c & 3) * 8 + ((c & 31) >> 2)] = rndtf(v);
}

#define CP16(dst, src) \
    asm volatile("cp.async.cg.shared.global [%0], [%1], 16;" :: "r"(dst), "l"(src) : "memory")
#define CPCOMMIT() asm volatile("cp.async.commit_group;" ::: "memory")
#define CPWAIT(n)  asm volatile("cp.async.wait_group %0;" :: "n"(n) : "memory")

__device__ __forceinline__ void mma_tf32(float c[4],
                                         float a0, float a1, float a2, float a3,
                                         float b0, float b1)
{
    asm volatile(
        "mma.sync.aligned.m16n8k8.row.col.f32.tf32.tf32.f32 "
        "{%0,%1,%2,%3}, {%4,%5,%6,%7}, {%8,%9}, {%0,%1,%2,%3};"
        : "+f"(c[0]), "+f"(c[1]), "+f"(c[2]), "+f"(c[3])
        : "r"(__float_as_uint(a0)), "r"(__float_as_uint(a1)),
          "r"(__float_as_uint(a2)), "r"(__float_as_uint(a3)),
          "r"(__float_as_uint(b0)), "r"(__float_as_uint(b1)));
}

// ---------------- tiling constants ----------------
#define TGM 128
#define TGN 64
#define TBK 32
#define SSTR 36
#define ASTG (TGM * SSTR)   // 4608 floats
#define BSTG (TGN * SSTR)   // 2304 floats
#define NSTG 4
#define TG_SMEM (NSTG * (ASTG + BSTG) * 4)   // 110592 B
#define QK_SMEM (2 * (ASTG + BSTG) * 4)      // 55296 B

// fragment load macro: fills aF[4][8], bF[4][8] from stage pointers
#define FRAG_LOADS(pA, pB)                                                            \
    _Pragma("unroll")                                                                 \
    for (int r = 0; r < 4; r++) {                                                     \
        const float* rp = (pA) + (wm + r * 8 + g) * SSTR + tig * 8;                   \
        *reinterpret_cast<float4*>(&aF[r][0]) = *reinterpret_cast<const float4*>(rp); \
        *reinterpret_cast<float4*>(&aF[r][4]) = *reinterpret_cast<const float4*>(rp + 4); \
    }                                                                                 \
    _Pragma("unroll")                                                                 \
    for (int r = 0; r < 4; r++) {                                                     \
        const float* rp = (pB) + (wn + r * 8 + g) * SSTR + tig * 8;                   \
        *reinterpret_cast<float4*>(&bF[r][0]) = *reinterpret_cast<const float4*>(rp); \
        *reinterpret_cast<float4*>(&bF[r][4]) = *reinterpret_cast<const float4*>(rp + 4); \
    }

#define MMA_BLOCK()                                                                   \
    _Pragma("unroll")                                                                 \
    for (int ks = 0; ks < 4; ks++)                                                    \
        _Pragma("unroll")                                                             \
        for (int mt = 0; mt < 2; mt++)                                                \
            _Pragma("unroll")                                                         \
            for (int nt = 0; nt < 4; nt++)                                            \
                mma_tf32(acc[mt][nt],                                                 \
                         aF[2 * mt][2 * ks], aF[2 * mt + 1][2 * ks],                  \
                         aF[2 * mt][2 * ks + 1], aF[2 * mt + 1][2 * ks + 1],          \
                         bF[nt][2 * ks], bF[nt][2 * ks + 1]);

// ---------------- prep ----------------
__global__ void prep_kernel(const float* __restrict__ x, const float* __restrict__ pos,
                            const int* __restrict__ ewp, float* __restrict__ enc)
{
    __shared__ float tile[32][33];
    int b  = blockIdx.z;
    int d0 = blockIdx.x * 32, t0 = blockIdx.y * 32;
    int tx = threadIdx.x, ty = threadIdx.y;
    const float* xb = x + (long long)b * D_ * T_;
    #pragma unroll
    for (int i = 0; i < 4; i++) {
        int d = ty + i * 8;
        tile[d][tx] = xb[(long long)(d0 + d) * T_ + t0 + tx];
    }
    __syncthreads();
    #pragma unroll
    for (int i = 0; i < 4; i++) {
        int tl = ty + i * 8;
        int t = t0 + tl, d = d0 + tx;
        int pr = ewp[t];
        enc[(((long long)b * T_) + t) * D_ + d] =
            tile[tx][tl] * 22.62741699796952f + pos[(long long)pr * D_ + d];
    }
}

// ---------------- weight transpose (perm+round) ----------------
struct WP { const float* w[NWMAT]; };
__global__ void wtrans_kernel(WP p, float* __restrict__ out)
{
    __shared__ float t[32][33];
    int mi = blockIdx.z;
    const float* W = p.w[mi];
    float* O = out + (long long)mi * D_ * D_;
    int n0 = blockIdx.x * 32, k0 = blockIdx.y * 32;
    int tx = threadIdx.x, ty = threadIdx.y;
    #pragma unroll
    for (int i = 0; i < 4; i++) {
        int k = k0 + ty + i * 8;
        t[ty + i * 8][tx] = W[(long long)k * D_ + n0 + tx];
    }
    __syncthreads();
    #pragma unroll
    for (int i = 0; i < 4; i++) {
        int n = n0 + ty + i * 8;
        O[(long long)n * D_ + k0 + (tx & 3) * 8 + (tx >> 2)] = rndtf(t[tx][ty + i * 8]);
    }
}

// ---------------- layernorm (perm+round output) ----------------
__global__ void ln_kernel(const float* __restrict__ in, float* __restrict__ out,
                          const float* __restrict__ gs, const float* __restrict__ gb)
{
    int row  = blockIdx.x * 8 + threadIdx.y;
    int lane = threadIdx.x;
    const float* r = in + (long long)row * D_;
    float4 xv[4];
    #pragma unroll
    for (int j = 0; j < 4; j++)
        xv[j] = *reinterpret_cast<const float4*>(&r[(j * 32 + lane) * 4]);
    float s = 0.f;
    #pragma unroll
    for (int j = 0; j < 4; j++) s += xv[j].x + xv[j].y + xv[j].z + xv[j].w;
    #pragma unroll
    for (int o = 16; o; o >>= 1) s += __shfl_xor_sync(0xffffffffu, s, o);
    float mean = s * (1.0f / D_);
    float vs = 0.f;
    #pragma unroll
    for (int j = 0; j < 4; j++) {
        float a = xv[j].x - mean, b2 = xv[j].y - mean, c = xv[j].z - mean, d = xv[j].w - mean;
        vs += a * a + b2 * b2 + c * c + d * d;
    }
    #pragma unroll
    for (int o = 16; o; o >>= 1) vs += __shfl_xor_sync(0xffffffffu, vs, o);
    float rstd = rsqrtf(vs * (1.0f / D_) + 1e-5f);
    float* w = out + (long long)row * D_;
    #pragma unroll
    for (int j = 0; j < 4; j++) {
        int c0 = (j * 32 + lane) * 4;
        float4 sv = *reinterpret_cast<const float4*>(&gs[c0]);
        float4 bv = *reinterpret_cast<const float4*>(&gb[c0]);
        float tx = (xv[j].x - mean) * rstd * sv.x + bv.x;
        float ty = (xv[j].y - mean) * rstd * sv.y + bv.y;
        float tz = (xv[j].z - mean) * rstd * sv.z + bv.z;
        float tw = (xv[j].w - mean) * rstd * sv.w + bv.w;
        float* wp = w + (c0 & ~31);
        int qq = (c0 & 31) >> 2;
        wp[qq]      = rndtf(tx);
        wp[8 + qq]  = rndtf(ty);
        wp[16 + qq] = rndtf(tz);
        wp[24 + qq] = rndtf(tw);
    }
}

// ---------------- softmax over rows of 256 (perm+round output for PV) ----------------
__global__ void softmax_kernel(float* __restrict__ P)
{
    long long row = (long long)blockIdx.x * 8 + threadIdx.y;
    float* r = P + row * T_;
    int lane = threadIdx.x;
    float4 a = *reinterpret_cast<const float4*>(&r[lane * 4]);
    float4 b = *reinterpret_cast<const float4*>(&r[128 + lane * 4]);
    float m = fmaxf(fmaxf(fmaxf(a.x, a.y), fmaxf(a.z, a.w)),
                    fmaxf(fmaxf(b.x, b.y), fmaxf(b.z, b.w)));
    #pragma unroll
    for (int o = 16; o; o >>= 1) m = fmaxf(m, __shfl_xor_sync(0xffffffffu, m, o));
    a.x = __expf(a.x - m); a.y = __expf(a.y - m); a.z = __expf(a.z - m); a.w = __expf(a.w - m);
    b.x = __expf(b.x - m); b.y = __expf(b.y - m); b.z = __expf(b.z - m); b.w = __expf(b.w - m);
    float s = a.x + a.y + a.z + a.w + b.x + b.y + b.z + b.w;
    #pragma unroll
    for (int o = 16; o; o >>= 1) s += __shfl_xor_sync(0xffffffffu, s, o);
    float inv = 1.0f / s;
    int c0 = lane * 4, c1 = 128 + lane * 4;
    st_perm(r, c0 + 0, a.x * inv); st_perm(r, c0 + 1, a.y * inv);
    st_perm(r, c0 + 2, a.z * inv); st_perm(r, c0 + 3, a.w * inv);
    st_perm(r, c1 + 0, b.x * inv); st_perm(r, c1 + 1, b.y * inv);
    st_perm(r, c1 + 2, b.z * inv); st_perm(r, c1 + 3, b.w * inv);
}

// ======================================================================
// 128x64 tf32 MMA GEMM, 4-stage cp.async, ONE barrier per K-tile.
// flags: bit0 relu, bit1 perm+round out, bit2 bias-per-row.
// ======================================================================
struct TGB { const float* Bt; float* C; const float* bias; const float* resid;
             int flags; int ldc; };
struct TGArgs { TGB t[2]; };

__global__ void __launch_bounds__(256, 2) tgemm_kernel(const float* __restrict__ A, TGArgs args)
{
    extern __shared__ float sm[];
    float* sA = sm;
    float* sB = sm + NSTG * ASTG;
    TGB tb = args.t[blockIdx.z];

    int tid = threadIdx.x, w = tid >> 5, lane = tid & 31;
    int g = lane >> 2, tig = lane & 3;
    int bm = blockIdx.y * TGM, bn = blockIdx.x * TGN;
    int wm = (w & 3) * 32, wn = (w >> 2) * 32;

    unsigned uA = (unsigned)__cvta_generic_to_shared(sA);
    unsigned uB = (unsigned)__cvta_generic_to_shared(sB);
    int crow = tid >> 3, cc4 = tid & 7;

    const float* aP[4]; const float* bP[2];
    unsigned dA[4], dB[2];
    #pragma unroll
    for (int i = 0; i < 4; i++) {
        aP[i] = A + (long long)(bm + crow + i * 32) * D_ + cc4 * 4;
        dA[i] = uA + (unsigned)(((crow + i * 32) * SSTR + cc4 * 4) * 4);
    }
    #pragma unroll
    for (int i = 0; i < 2; i++) {
        bP[i] = tb.Bt + (long long)(bn + crow + i * 32) * D_ + cc4 * 4;
        dB[i] = uB + (unsigned)(((crow + i * 32) * SSTR + cc4 * 4) * 4);
    }

    float acc[2][4][4];
    #pragma unroll
    for (int i = 0; i < 2; i++)
        #pragma unroll
        for (int j = 0; j < 4; j++)
            #pragma unroll
            for (int q = 0; q < 4; q++) acc[i][j][q] = 0.f;

    #pragma unroll
    for (int s = 0; s < 3; s++) {
        #pragma unroll
        for (int i = 0; i < 4; i++) CP16(dA[i] + (unsigned)(s * ASTG * 4), aP[i] + s * TBK);
        #pragma unroll
        for (int i = 0; i < 2; i++) CP16(dB[i] + (unsigned)(s * BSTG * 4), bP[i] + s * TBK);
        CPCOMMIT();
    }

    const int NKT = D_ / TBK;   // 16
    for (int kt = 0; kt < NKT; kt++) {
        CPWAIT(2);
        __syncthreads();
        int s = kt & 3;
        const float* pA = sA + s * ASTG;
        const float* pB = sB + s * BSTG;
        float aF[4][8], bF[4][8];
        FRAG_LOADS(pA, pB)

        if (kt + 3 < NKT) {
            int rs = (kt + 3) & 3;
            int ko = (kt + 3) * TBK;
            #pragma unroll
            for (int i = 0; i < 4; i++) CP16(dA[i] + (unsigned)(rs * ASTG * 4), aP[i] + ko);
            #pragma unroll
            for (int i = 0; i < 2; i++) CP16(dB[i] + (unsigned)(rs * BSTG * 4), bP[i] + ko);
        }
        CPCOMMIT();
        MMA_BLOCK()
    }

    int flags = tb.flags, ldc = tb.ldc;
    #pragma unroll
    for (int mt = 0; mt < 2; mt++) {
        #pragma unroll
        for (int nt = 0; nt < 4; nt++) {
            int row0 = bm + wm + mt * 16 + g;
            int col  = bn + wn + nt * 8 + 2 * tig;
            float v00 = acc[mt][nt][0], v01 = acc[mt][nt][1];
            float v10 = acc[mt][nt][2], v11 = acc[mt][nt][3];
            if (flags & 4) {
                float b0 = tb.bias[row0], b1 = tb.bias[row0 + 8];
                v00 += b0; v01 += b0; v10 += b1; v11 += b1;
            } else {
                float2 bv = *reinterpret_cast<const float2*>(&tb.bias[col]);
                v00 += bv.x; v01 += bv.y; v10 += bv.x; v11 += bv.y;
            }
            if (flags & 1) {
                v00 = fmaxf(v00, 0.f); v01 = fmaxf(v01, 0.f);
                v10 = fmaxf(v10, 0.f); v11 = fmaxf(v11, 0.f);
            }
            if (tb.resid) {
                float2 r0 = *reinterpret_cast<const float2*>(
                    &tb.resid[(long long)row0 * ldc + col]);
                float2 r1 = *reinterpret_cast<const float2*>(
                    &tb.resid[(long long)(row0 + 8) * ldc + col]);
                v00 += r0.x; v01 += r0.y; v10 += r1.x; v11 += r1.y;
            }
            if (flags & 2) {
                float* r0p = &tb.C[(long long)row0 * ldc];
                float* r1p = &tb.C[(long long)(row0 + 8) * ldc];
                st_perm(r0p, col, v00); st_perm(r0p, col + 1, v01);
                st_perm(r1p, col, v10); st_perm(r1p, col + 1, v11);
            } else {
                *reinterpret_cast<float2*>(&tb.C[(long long)row0 * ldc + col]) =
                    make_float2(v00, v01);
                *reinterpret_cast<float2*>(&tb.C[(long long)(row0 + 8) * ldc + col]) =
                    make_float2(v10, v11);
            }
        }
    }
}

// ======================================================================
// QK^T: per (b,h): P[128x64 tiles] = Q @ K^T * 0.125.  K-dim = 64 (2 tiles).
// ======================================================================
__global__ void __launch_bounds__(256, 2) qk_kernel(
    const float* __restrict__ q, const float* __restrict__ k, float* __restrict__ P)
{
    extern __shared__ float sm[];
    float* sA = sm;
    float* sB = sm + 2 * ASTG;

    int z = blockIdx.z, b = z >> 3, h = z & 7;
    int tid = threadIdx.x, w = tid >> 5, lane = tid & 31;
    int g = lane >> 2, tig = lane & 3;
    int bm = blockIdx.y * TGM, bn = blockIdx.x * TGN;
    int wm = (w & 3) * 32, wn = (w >> 2) * 32;

    unsigned uA = (unsigned)__cvta_generic_to_shared(sA);
    unsigned uB = (unsigned)__cvta_generic_to_shared(sB);
    int crow = tid >> 3, cc4 = tid & 7;

    const float* aP[4]; const float* bP[2];
    unsigned dA[4], dB[2];
    #pragma unroll
    for (int i = 0; i < 4; i++) {
        aP[i] = q + (long long)(b * T_ + bm + crow + i * 32) * D_ + h * DK_ + cc4 * 4;
        dA[i] = uA + (unsigned)(((crow + i * 32) * SSTR + cc4 * 4) * 4);
    }
    #pragma unroll
    for (int i = 0; i < 2; i++) {
        bP[i] = k + (long long)(b * T_ + bn + crow + i * 32) * D_ + h * DK_ + cc4 * 4;
        dB[i] = uB + (unsigned)(((crow + i * 32) * SSTR + cc4 * 4) * 4);
    }

    float acc[2][4][4];
    #pragma unroll
    for (int i = 0; i < 2; i++)
        #pragma unroll
        for (int j = 0; j < 4; j++)
            #pragma unroll
            for (int qq = 0; qq < 4; qq++) acc[i][j][qq] = 0.f;

    #pragma unroll
    for (int s = 0; s < 2; s++) {
        #pragma unroll
        for (int i = 0; i < 4; i++) CP16(dA[i] + (unsigned)(s * ASTG * 4), aP[i] + s * TBK);
        #pragma unroll
        for (int i = 0; i < 2; i++) CP16(dB[i] + (unsigned)(s * BSTG * 4), bP[i] + s * TBK);
        CPCOMMIT();
    }

    {
        CPWAIT(1);
        __syncthreads();
        float aF[4][8], bF[4][8];
        FRAG_LOADS(sA, sB)
        MMA_BLOCK()
    }
    {
        CPWAIT(0);
        __syncthreads();
        float aF[4][8], bF[4][8];
        FRAG_LOADS(sA + ASTG, sB + BSTG)
        MMA_BLOCK()
    }

    float* C = P + (long long)z * T_ * T_;
    #pragma unroll
    for (int mt = 0; mt < 2; mt++)
        #pragma unroll
        for (int nt = 0; nt < 4; nt++) {
            int row0 = bm + wm + mt * 16 + g;
            int col  = bn + wn + nt * 8 + 2 * tig;
            *reinterpret_cast<float2*>(&C[(long long)row0 * T_ + col]) =
                make_float2(acc[mt][nt][0] * 0.125f, acc[mt][nt][1] * 0.125f);
            *reinterpret_cast<float2*>(&C[(long long)(row0 + 8) * T_ + col]) =
                make_float2(acc[mt][nt][2] * 0.125f, acc[mt][nt][3] * 0.125f);
        }
}

// ======================================================================
// PV: per (b,h): O[t, dh] = P[t, t'] @ V^T[dh, t']^T.  K=256 (8 tiles).
// P perm-rounded by softmax; vT perm-rounded [512, 8192]. Out perm-rounded.
// ======================================================================
__global__ void __launch_bounds__(256, 2) pv_kernel(
    const float* __restrict__ P, const float* __restrict__ vT, float* __restrict__ O)
{
    extern __shared__ float sm[];
    float* sA = sm;
    float* sB = sm + NSTG * ASTG;

    int z = blockIdx.z, b = z >> 3, h = z & 7;
    int tid = threadIdx.x, w = tid >> 5, lane = tid & 31;
    int g = lane >> 2, tig = lane & 3;
    int bm = blockIdx.y * TGM;
    int wm = (w & 3) * 32, wn = (w >> 2) * 32;

    unsigned uA = (unsigned)__cvta_generic_to_shared(sA);
    unsigned uB = (unsigned)__cvta_generic_to_shared(sB);
    int crow = tid >> 3, cc4 = tid & 7;

    const float* aP[4]; const float* bP[2];
    unsigned dA[4], dB[2];
    #pragma unroll
    for (int i = 0; i < 4; i++) {
        aP[i] = P + (long long)z * T_ * T_ + (long long)(bm + crow + i * 32) * T_ + cc4 * 4;
        dA[i] = uA + (unsigned)(((crow + i * 32) * SSTR + cc4 * 4) * 4);
    }
    #pragma unroll
    for (int i = 0; i < 2; i++) {
        bP[i] = vT + (long long)(h * DK_ + crow + i * 32) * (B_ * T_) + b * T_ + cc4 * 4;
        dB[i] = uB + (unsigned)(((crow + i * 32) * SSTR + cc4 * 4) * 4);
    }

    float acc[2][4][4];
    #pragma unroll
    for (int i = 0; i < 2; i++)
        #pragma unroll
        for (int j = 0; j < 4; j++)
            #pragma unroll
            for (int q = 0; q < 4; q++) acc[i][j][q] = 0.f;

    #pragma unroll
    for (int s = 0; s < 3; s++) {
        #pragma unroll
        for (int i = 0; i < 4; i++) CP16(dA[i] + (unsigned)(s * ASTG * 4), aP[i] + s * TBK);
        #pragma unroll
        for (int i = 0; i < 2; i++) CP16(dB[i] + (unsigned)(s * BSTG * 4), bP[i] + s * TBK);
        CPCOMMIT();
    }

    const int NKT = T_ / TBK;   // 8
    for (int kt = 0; kt < NKT; kt++) {
        CPWAIT(2);
        __syncthreads();
        int s = kt & 3;
        const float* pA = sA + s * ASTG;
        const float* pB = sB + s * BSTG;
        float aF[4][8], bF[4][8];
        FRAG_LOADS(pA, pB)

        if (kt + 3 < NKT) {
            int rs = (kt + 3) & 3;
            int ko = (kt + 3) * TBK;
            #pragma unroll
            for (int i = 0; i < 4; i++) CP16(dA[i] + (unsigned)(rs * ASTG * 4), aP[i] + ko);
            #pragma unroll
            for (int i = 0; i < 2; i++) CP16(dB[i] + (unsigned)(rs * BSTG * 4), bP[i] + ko);
        }
        CPCOMMIT();
        MMA_BLOCK()
    }

    #pragma unroll
    for (int mt = 0; mt < 2; mt++)
        #pragma unroll
        for (int nt = 0; nt < 4; nt++) {
            int gr   = b * T_ + bm + wm + mt * 16 + g;
            int colg = h * DK_ + wn + nt * 8 + 2 * tig;
            float* r0p = &O[(long long)gr * D_];
            float* r1p = &O[(long long)(gr + 8) * D_];
            st_perm(r0p, colg, acc[mt][nt][0]); st_perm(r0p, colg + 1, acc[mt][nt][1]);
            st_perm(r1p, colg, acc[mt][nt][2]); st_perm(r1p, colg + 1, acc[mt][nt][3]);
        }
}

// ---------------- PVAM head: 5 query positions per block ----------------
__global__ void __launch_bounds__(256) pvam_kernel(
    const float* __restrict__ wf, const float* __restrict__ emb,
    const int* __restrict__ gwp, const float* __restrict__ fc1,
    float* __restrict__ out)
{
    __shared__ float s_wp[5][D_];
    __shared__ float s_f[D_];
    __shared__ float s_sc[5][T_];
    __shared__ float s_red[40];
    int mg = blockIdx.x * 5, b = blockIdx.y;
    int tid = threadIdx.x;
    for (int i = tid; i < 5 * D_; i += 256) {
        int j = i >> 9, c = i & (D_ - 1);
        s_wp[j][c] = emb[(long long)gwp[mg + j] * D_ + c];
    }
    for (int i = tid; i < D_; i += 256) s_f[i] = fc1[i];
    __syncthreads();

    // phase A: per-thread token t=tid, 5 scores
    const float* wr = wf + ((long long)b * T_ + tid) * D_;
    float sc[5] = {0.f, 0.f, 0.f, 0.f, 0.f};
    for (int c4 = 0; c4 < D_ / 4; c4++) {
        float4 wv = *reinterpret_cast<const float4*>(&wr[c4 * 4]);
        float4 fv = *reinterpret_cast<const float4*>(&s_f[c4 * 4]);
        #pragma unroll
        for (int j = 0; j < 5; j++) {
            float4 pv = *reinterpret_cast<const float4*>(&s_wp[j][c4 * 4]);
            sc[j] += tanh_fast(wv.x + pv.x) * fv.x;
            sc[j] += tanh_fast(wv.y + pv.y) * fv.y;
            sc[j] += tanh_fast(wv.z + pv.z) * fv.z;
            sc[j] += tanh_fast(wv.w + pv.w) * fv.w;
        }
    }

    int wid = tid >> 5, lane = tid & 31;
    #pragma unroll
    for (int j = 0; j < 5; j++) {
        float mv = sc[j];
        #pragma unroll
        for (int o = 16; o; o >>= 1) mv = fmaxf(mv, __shfl_xor_sync(0xffffffffu, mv, o));
        if (lane == 0) s_red[wid] = mv;
        __syncthreads();
        if (tid < 32) {
            float t = (tid < 8) ? s_red[tid] : -3.0e38f;
            #pragma unroll
            for (int o = 4; o; o >>= 1) t = fmaxf(t, __shfl_xor_sync(0xffffffffu, t, o));
            if (tid == 0) s_red[32] = t;
        }
        __syncthreads();
        float e = __expf(sc[j] - s_red[32]);
        float sv = e;
        #pragma unroll
        for (int o = 16; o; o >>= 1) sv += __shfl_xor_sync(0xffffffffu, sv, o);
        if (lane == 0) s_red[8 + wid] = sv;
        __syncthreads();
        if (tid < 32) {
            float t = (tid < 8) ? s_red[8 + tid] : 0.f;
            #pragma unroll
            for (int o = 4; o; o >>= 1) t += __shfl_xor_sync(0xffffffffu, t, o);
            if (tid == 0) s_red[33] = t;
        }
        __syncthreads();
        s_sc[j][tid] = e * (1.0f / s_red[33]);
        __syncthreads();
    }

    // phase B: out[b, mg+j, c] = sum_t attn[j][t] * wf[b,t,c]
    const float* base = wf + (long long)b * T_ * D_;
    int c0 = tid, c1 = tid + 256;
    float a0[5] = {0.f, 0.f, 0.f, 0.f, 0.f};
    float a1[5] = {0.f, 0.f, 0.f, 0.f, 0.f};
    #pragma unroll 4
    for (int t = 0; t < T_; t++) {
        float w0 = base[(long long)t * D_ + c0];
        float w1 = base[(long long)t * D_ + c1];
        #pragma unroll
        for (int j = 0; j < 5; j++) {
            float s = s_sc[j][t];
            a0[j] += s * w0;
            a1[j] += s * w1;
        }
    }
    #pragma unroll
    for (int j = 0; j < 5; j++) {
        long long ob = ((long long)b * ML_ + mg + j) * D_;
        out[ob + c0] = a0[j];
        out[ob + c1] = a1[j];
    }
}

// ---------------- host launcher ----------------
extern "C" void kernel_launch(void* const* d_in, const int* in_sizes, int n_in,
                              void* d_out, int out_size)
{
    const float* x    = (const float*)d_in[0];
    const int*   ewp  = (const int*)  d_in[1];
    const int*   gwp  = (const int*)  d_in[2];
    const float* pos  = (const float*)d_in[3];
    const float* ln1s = (const float*)d_in[4];
    const float* ln1b = (const float*)d_in[5];
    const float* Wq   = (const float*)d_in[6];
    const float* bq   = (const float*)d_in[7];
    const float* Wk   = (const float*)d_in[8];
    const float* bk   = (const float*)d_in[9];
    const float* Wv   = (const float*)d_in[10];
    const float* bv   = (const float*)d_in[11];
    const float* Wo   = (const float*)d_in[12];
    const float* bo   = (const float*)d_in[13];
    const float* ln2s = (const float*)d_in[14];
    const float* ln2b = (const float*)d_in[15];
    const float* W1   = (const float*)d_in[16];
    const float* b1   = (const float*)d_in[17];
    const float* W2   = (const float*)d_in[18];
    const float* b2   = (const float*)d_in[19];
    const float* lnfs = (const float*)d_in[20];
    const float* lnfb = (const float*)d_in[21];
    const float* fc0w = (const float*)d_in[22];
    const float* fc0b = (const float*)d_in[23];
    const float* emb  = (const float*)d_in[24];
    const float* fc1  = (const float*)d_in[25];

    static float *enc = nullptr, *tmp, *q, *k, *v, *o, *p, *wT;
    if (!enc) {
        cudaGetSymbolAddress((void**)&enc, g_enc);
        cudaGetSymbolAddress((void**)&tmp, g_tmp);
        cudaGetSymbolAddress((void**)&q,   g_q);
        cudaGetSymbolAddress((void**)&k,   g_k);
        cudaGetSymbolAddress((void**)&v,   g_v);
        cudaGetSymbolAddress((void**)&o,   g_o);
        cudaGetSymbolAddress((void**)&p,   g_p);
        cudaGetSymbolAddress((void**)&wT,  g_wT);
        cudaFuncSetAttribute(tgemm_kernel,
                             cudaFuncAttributeMaxDynamicSharedMemorySize, TG_SMEM);
        cudaFuncSetAttribute(qk_kernel,
                             cudaFuncAttributeMaxDynamicSharedMemorySize, QK_SMEM);
        cudaFuncSetAttribute(pv_kernel,
                             cudaFuncAttributeMaxDynamicSharedMemorySize, TG_SMEM);
    }

    const long long DD = (long long)D_ * D_;

    WP wp;
    wp.w[0]  = Wq;       wp.w[1]  = Wk;       wp.w[2]  = Wv;
    wp.w[3]  = Wo;       wp.w[4]  = W1;       wp.w[5]  = W2;
    wp.w[6]  = Wq + DD;  wp.w[7]  = Wk + DD;  wp.w[8]  = Wv + DD;
    wp.w[9]  = Wo + DD;  wp.w[10] = W1 + DD;  wp.w[11] = W2 + DD;
    wp.w[12] = fc0w;
    wtrans_kernel<<<dim3(16, 16, NWMAT), dim3(32, 8)>>>(wp, wT);

    prep_kernel<<<dim3(D_ / 32, T_ / 32, B_), dim3(32, 8)>>>(x, pos, ewp, enc);

    const int MT = B_ * T_;                        // 8192
    const dim3 tg1(D_ / TGN, MT / TGM, 1);         // (8, 64)
    const dim3 tg2(D_ / TGN, MT / TGM, 2);
    const dim3 tgv(MT / TGN, D_ / TGM, 1);         // (128, 4) for V^T

    for (int l = 0; l < L_; l++) {
        int vo = l * D_;
        const float* wq = wT + (l * 6 + 0) * DD;
        const float* wk = wT + (l * 6 + 1) * DD;
        const float* wv = wT + (l * 6 + 2) * DD;
        const float* wo = wT + (l * 6 + 3) * DD;
        const float* w1 = wT + (l * 6 + 4) * DD;
        const float* w2 = wT + (l * 6 + 5) * DD;

        ln_kernel<<<MT / 8, dim3(32, 8)>>>(enc, tmp, ln1s + vo, ln1b + vo);

        TGArgs aqk;
        aqk.t[0] = {wq, q, bq + vo, nullptr, 2, D_};
        aqk.t[1] = {wk, k, bk + vo, nullptr, 2, D_};
        tgemm_kernel<<<tg2, 256, TG_SMEM>>>(tmp, aqk);

        // V^T[512, 8192] = Wv @ tmp^T  (per-row bias, perm+round)
        TGArgs av;
        av.t[0] = {tmp, v, bv + vo, nullptr, 2 | 4, MT};
        tgemm_kernel<<<tgv, 256, TG_SMEM>>>(wv, av);

        qk_kernel<<<dim3(T_ / TGN, T_ / TGM, B_ * NH_), 256, QK_SMEM>>>(q, k, p);
        softmax_kernel<<<(B_ * NH_ * T_) / 8, dim3(32, 8)>>>(p);
        pv_kernel<<<dim3(1, T_ / TGM, B_ * NH_), 256, TG_SMEM>>>(p, v, o);

        TGArgs ao; ao.t[0] = {wo, enc, bo + vo, enc, 0, D_};
        tgemm_kernel<<<tg1, 256, TG_SMEM>>>(o, ao);

        ln_kernel<<<MT / 8, dim3(32, 8)>>>(enc, tmp, ln2s + vo, ln2b + vo);
        TGArgs a1; a1.t[0] = {w1, o, b1 + vo, nullptr, 3, D_};
        tgemm_kernel<<<tg1, 256, TG_SMEM>>>(tmp, a1);
        TGArgs a2; a2.t[0] = {w2, enc, b2 + vo, enc, 0, D_};
        tgemm_kernel<<<tg1, 256, TG_SMEM>>>(o, a2);
    }

    ln_kernel<<<MT / 8, dim3(32, 8)>>>(enc, tmp, lnfs, lnfb);
    TGArgs af; af.t[0] = {wT + 12 * DD, q, fc0b, nullptr, 0, D_};
    tgemm_kernel<<<tg1, 256, TG_SMEM>>>(tmp, af);

    pvam_kernel<<<dim3(ML_ / 5, B_), 256>>>(q, emb, gwp, fc1, (float*)d_out);
}

// round 7
// speedup vs baseline: 2.1905x; 1.7790x over previous
#include <cuda_runtime.h>
#include <cuda_fp16.h>
#include <math.h>

// ---------------- problem constants ----------------
#define B_  32
#define T_  256
#define D_  512
#define NH_ 8
#define DK_ 64
#define L_  2
#define ML_ 25
#define NWMAT 13

// ---------------- scratch ----------------
__device__ float g_enc[B_*T_*D_];
__device__ float g_tmp[B_*T_*D_];
__device__ float g_q  [B_*T_*D_];
__device__ float g_k  [B_*T_*D_];
__device__ float g_v  [B_*T_*D_];   // V^T halves [512, 8192]
__device__ float g_o  [B_*T_*D_];
__device__ float g_p  [B_*NH_*T_*T_];
__device__ float g_wT [NWMAT*D_*D_];  // halves, perm layout

__device__ __forceinline__ float tanh_fast(float x) {
    float y;
    asm("tanh.approx.f32 %0, %1;" : "=f"(y) : "f"(x));
    return y;
}
// fp16 fragment k-permutation within a 32-block:
// k = blk*16 + oct*8 + 2*tig + b  ->  pos = tig*8 + blk*4 + oct*2 + b
__device__ __forceinline__ int pidx32(int k) {
    return ((k & 6) >> 1) * 8 + ((k >> 4) & 1) * 4 + ((k >> 3) & 1) * 2 + (k & 1);
}
__device__ __forceinline__ void st_perm_h2(__half* rowp, int c, float v0, float v1) {
    // c even: positions p, p+1 within block
    *reinterpret_cast<__half2*>(&rowp[(c & ~31) + pidx32(c & 31)]) = __floats2half2_rn(v0, v1);
}

#define CP16(dst, src) \
    asm volatile("cp.async.cg.shared.global [%0], [%1], 16;" :: "r"(dst), "l"(src) : "memory")
#define CPCOMMIT() asm volatile("cp.async.commit_group;" ::: "memory")
#define CPWAIT(n)  asm volatile("cp.async.wait_group %0;" :: "n"(n) : "memory")

__device__ __forceinline__ void mma_f16(float c[4],
                                        unsigned a0, unsigned a1, unsigned a2, unsigned a3,
                                        unsigned b0, unsigned b1)
{
    asm volatile(
        "mma.sync.aligned.m16n8k16.row.col.f32.f16.f16.f32 "
        "{%0,%1,%2,%3}, {%4,%5,%6,%7}, {%8,%9}, {%0,%1,%2,%3};"
        : "+f"(c[0]), "+f"(c[1]), "+f"(c[2]), "+f"(c[3])
        : "r"(a0), "r"(a1), "r"(a2), "r"(a3), "r"(b0), "r"(b1));
}

// ---------------- tiling ----------------
// CTA 128x64, BK=64 halves, 8 warps of 32x32. Stage: A 16KB, B 8KB. 4 stages.
#define ABYT 16384
#define BBYT 8192
#define NSTG 4
#define TG_SMEM (NSTG * (ABYT + BBYT))   // 98304
#define QK_SMEM (ABYT + BBYT)            // 24576

// loads fragments for one 32-k sub-block and issues 16 MMAs
#define MMA_SUB(stgA, stgB, s32) {                                                    \
    uint4 aU[4], bU[4];                                                               \
    _Pragma("unroll")                                                                 \
    for (int r2 = 0; r2 < 4; r2++) {                                                  \
        int row = wm + r2 * 8 + g;                                                    \
        aU[r2] = *reinterpret_cast<const uint4*>(                                     \
            (stgA) + row * 128 + ((((s32) * 64 + tig * 16)) ^ ((row & 1) << 6)));     \
        int rob = wn + r2 * 8 + g;                                                    \
        bU[r2] = *reinterpret_cast<const uint4*>(                                     \
            (stgB) + rob * 128 + ((((s32) * 64 + tig * 16)) ^ ((rob & 1) << 6)));     \
    }                                                                                 \
    _Pragma("unroll")                                                                 \
    for (int mt = 0; mt < 2; mt++)                                                    \
        _Pragma("unroll")                                                             \
        for (int nt = 0; nt < 4; nt++) {                                              \
            mma_f16(acc[mt][nt], aU[2*mt].x, aU[2*mt+1].x, aU[2*mt].y, aU[2*mt+1].y,  \
                    bU[nt].x, bU[nt].y);                                              \
            mma_f16(acc[mt][nt], aU[2*mt].z, aU[2*mt+1].z, aU[2*mt].w, aU[2*mt+1].w,  \
                    bU[nt].z, bU[nt].w);                                              \
        }                                                                             \
}

// ---------------- prep ----------------
__global__ void prep_kernel(const float* __restrict__ x, const float* __restrict__ pos,
                            const int* __restrict__ ewp, float* __restrict__ enc)
{
    __shared__ float tile[32][33];
    int b  = blockIdx.z;
    int d0 = blockIdx.x * 32, t0 = blockIdx.y * 32;
    int tx = threadIdx.x, ty = threadIdx.y;
    const float* xb = x + (long long)b * D_ * T_;
    #pragma unroll
    for (int i = 0; i < 4; i++) {
        int d = ty + i * 8;
        tile[d][tx] = xb[(long long)(d0 + d) * T_ + t0 + tx];
    }
    __syncthreads();
    #pragma unroll
    for (int i = 0; i < 4; i++) {
        int tl = ty + i * 8;
        int t = t0 + tl, d = d0 + tx;
        int pr = ewp[t];
        enc[(((long long)b * T_) + t) * D_ + d] =
            tile[tx][tl] * 22.62741699796952f + pos[(long long)pr * D_ + d];
    }
}

// ---------------- weight transpose -> half perm ----------------
struct WP { const float* w[NWMAT]; };
__global__ void wtrans_kernel(WP p, __half* __restrict__ out)
{
    __shared__ float t[32][33];
    int mi = blockIdx.z;
    const float* W = p.w[mi];
    __half* O = out + (long long)mi * D_ * D_;
    int n0 = blockIdx.x * 32, k0 = blockIdx.y * 32;
    int tx = threadIdx.x, ty = threadIdx.y;
    #pragma unroll
    for (int i = 0; i < 4; i++) {
        int k = k0 + ty + i * 8;
        t[ty + i * 8][tx] = W[(long long)k * D_ + n0 + tx];
    }
    __syncthreads();
    #pragma unroll
    for (int i = 0; i < 4; i++) {
        int n = n0 + ty + i * 8;
        O[(long long)n * D_ + k0 + pidx32(tx)] = __float2half(t[tx][ty + i * 8]);
    }
}

// ---------------- layernorm -> half perm ----------------
__global__ void ln_kernel(const float* __restrict__ in, __half* __restrict__ out,
                          const float* __restrict__ gs, const float* __restrict__ gb)
{
    int row  = blockIdx.x * 8 + threadIdx.y;
    int lane = threadIdx.x;
    const float* r = in + (long long)row * D_;
    float4 xv[4];
    #pragma unroll
    for (int j = 0; j < 4; j++)
        xv[j] = *reinterpret_cast<const float4*>(&r[(j * 32 + lane) * 4]);
    float s = 0.f;
    #pragma unroll
    for (int j = 0; j < 4; j++) s += xv[j].x + xv[j].y + xv[j].z + xv[j].w;
    #pragma unroll
    for (int o = 16; o; o >>= 1) s += __shfl_xor_sync(0xffffffffu, s, o);
    float mean = s * (1.0f / D_);
    float vs = 0.f;
    #pragma unroll
    for (int j = 0; j < 4; j++) {
        float a = xv[j].x - mean, b2 = xv[j].y - mean, c = xv[j].z - mean, d = xv[j].w - mean;
        vs += a * a + b2 * b2 + c * c + d * d;
    }
    #pragma unroll
    for (int o = 16; o; o >>= 1) vs += __shfl_xor_sync(0xffffffffu, vs, o);
    float rstd = rsqrtf(vs * (1.0f / D_) + 1e-5f);
    __half* w = out + (long long)row * D_;
    #pragma unroll
    for (int j = 0; j < 4; j++) {
        int c0 = (j * 32 + lane) * 4;
        float4 sv = *reinterpret_cast<const float4*>(&gs[c0]);
        float4 bv = *reinterpret_cast<const float4*>(&gb[c0]);
        float tx = (xv[j].x - mean) * rstd * sv.x + bv.x;
        float ty = (xv[j].y - mean) * rstd * sv.y + bv.y;
        float tz = (xv[j].z - mean) * rstd * sv.z + bv.z;
        float tw = (xv[j].w - mean) * rstd * sv.w + bv.w;
        st_perm_h2(w, c0,     tx, ty);
        st_perm_h2(w, c0 + 2, tz, tw);
    }
}

// ---------------- softmax (fp32 in, half perm out in place, pitch 512h) ----------------
__global__ void softmax_kernel(float* __restrict__ P)
{
    long long row = (long long)blockIdx.x * 8 + threadIdx.y;
    float* r = P + row * T_;
    int lane = threadIdx.x;
    float4 a = *reinterpret_cast<const float4*>(&r[lane * 4]);
    float4 b = *reinterpret_cast<const float4*>(&r[128 + lane * 4]);
    float m = fmaxf(fmaxf(fmaxf(a.x, a.y), fmaxf(a.z, a.w)),
                    fmaxf(fmaxf(b.x, b.y), fmaxf(b.z, b.w)));
    #pragma unroll
    for (int o = 16; o; o >>= 1) m = fmaxf(m, __shfl_xor_sync(0xffffffffu, m, o));
    a.x = __expf(a.x - m); a.y = __expf(a.y - m); a.z = __expf(a.z - m); a.w = __expf(a.w - m);
    b.x = __expf(b.x - m); b.y = __expf(b.y - m); b.z = __expf(b.z - m); b.w = __expf(b.w - m);
    float s = a.x + a.y + a.z + a.w + b.x + b.y + b.z + b.w;
    #pragma unroll
    for (int o = 16; o; o >>= 1) s += __shfl_xor_sync(0xffffffffu, s, o);
    float inv = 1.0f / s;
    __syncwarp();
    __half* rh = reinterpret_cast<__half*>(r);
    int c0 = lane * 4, c1 = 128 + lane * 4;
    st_perm_h2(rh, c0,     a.x * inv, a.y * inv);
    st_perm_h2(rh, c0 + 2, a.z * inv, a.w * inv);
    st_perm_h2(rh, c1,     b.x * inv, b.y * inv);
    st_perm_h2(rh, c1 + 2, b.z * inv, b.w * inv);
}

// ======================================================================
// fp16 MMA GEMM: C[M,512like] = A @ Bt^T (+bias)(+relu)(+resid), K=512.
// flags: bit0 relu, bit1 half-perm out, bit2 bias-per-row.
// ======================================================================
struct TGB { const __half* Bt; void* C; const float* bias; const float* resid;
             int flags; int ldc; };
struct TGArgs { TGB t[2]; };

__global__ void __launch_bounds__(256, 2) tgemm_kernel(const __half* __restrict__ A, TGArgs args)
{
    extern __shared__ char smc[];
    char* sA = smc;
    char* sB = smc + NSTG * ABYT;
    TGB tb = args.t[blockIdx.z];

    int tid = threadIdx.x, w = tid >> 5, lane = tid & 31;
    int g = lane >> 2, tig = lane & 3;
    int bm = blockIdx.y * 128, bn = blockIdx.x * 64;
    int wm = (w & 3) * 32, wn = (w >> 2) * 32;

    unsigned uA = (unsigned)__cvta_generic_to_shared(sA);
    unsigned uB = (unsigned)__cvta_generic_to_shared(sB);
    int crow = tid >> 3, cch = tid & 7;
    unsigned cxor = (unsigned)((cch * 16) ^ ((crow & 1) << 6));

    const __half* aP[4]; const __half* bP[2];
    unsigned dA[4], dB[2];
    #pragma unroll
    for (int i = 0; i < 4; i++) {
        aP[i] = A + (long long)(bm + crow + i * 32) * D_ + cch * 8;
        dA[i] = uA + (unsigned)((crow + i * 32) * 128) + cxor;
    }
    #pragma unroll
    for (int i = 0; i < 2; i++) {
        bP[i] = tb.Bt + (long long)(bn + crow + i * 32) * D_ + cch * 8;
        dB[i] = uB + (unsigned)((crow + i * 32) * 128) + cxor;
    }

    float acc[2][4][4];
    #pragma unroll
    for (int i = 0; i < 2; i++)
        #pragma unroll
        for (int j = 0; j < 4; j++)
            #pragma unroll
            for (int q = 0; q < 4; q++) acc[i][j][q] = 0.f;

    #pragma unroll
    for (int s = 0; s < 3; s++) {
        #pragma unroll
        for (int i = 0; i < 4; i++) CP16(dA[i] + (unsigned)(s * ABYT), aP[i] + s * 64);
        #pragma unroll
        for (int i = 0; i < 2; i++) CP16(dB[i] + (unsigned)(s * BBYT), bP[i] + s * 64);
        CPCOMMIT();
    }

    const int NKT = D_ / 64;   // 8
    for (int kt = 0; kt < NKT; kt++) {
        CPWAIT(2);
        __syncthreads();
        int s = kt & 3;
        char* pA = sA + s * ABYT;
        char* pB = sB + s * BBYT;
        if (kt + 3 < NKT) {
            int rs = (kt + 3) & 3;
            int ko = (kt + 3) * 64;
            #pragma unroll
            for (int i = 0; i < 4; i++) CP16(dA[i] + (unsigned)(rs * ABYT), aP[i] + ko);
            #pragma unroll
            for (int i = 0; i < 2; i++) CP16(dB[i] + (unsigned)(rs * BBYT), bP[i] + ko);
        }
        CPCOMMIT();
        MMA_SUB(pA, pB, 0)
        MMA_SUB(pA, pB, 1)
    }

    int flags = tb.flags, ldc = tb.ldc;
    #pragma unroll
    for (int mt = 0; mt < 2; mt++) {
        #pragma unroll
        for (int nt = 0; nt < 4; nt++) {
            int row0 = bm + wm + mt * 16 + g;
            int col  = bn + wn + nt * 8 + 2 * tig;
            float v00 = acc[mt][nt][0], v01 = acc[mt][nt][1];
            float v10 = acc[mt][nt][2], v11 = acc[mt][nt][3];
            if (flags & 4) {
                float b0 = tb.bias[row0], b1 = tb.bias[row0 + 8];
                v00 += b0; v01 += b0; v10 += b1; v11 += b1;
            } else {
                float2 bv = *reinterpret_cast<const float2*>(&tb.bias[col]);
                v00 += bv.x; v01 += bv.y; v10 += bv.x; v11 += bv.y;
            }
            if (flags & 1) {
                v00 = fmaxf(v00, 0.f); v01 = fmaxf(v01, 0.f);
                v10 = fmaxf(v10, 0.f); v11 = fmaxf(v11, 0.f);
            }
            if (tb.resid) {
                float2 r0 = *reinterpret_cast<const float2*>(
                    &tb.resid[(long long)row0 * ldc + col]);
                float2 r1 = *reinterpret_cast<const float2*>(
                    &tb.resid[(long long)(row0 + 8) * ldc + col]);
                v00 += r0.x; v01 += r0.y; v10 += r1.x; v11 += r1.y;
            }
            if (flags & 2) {
                __half* r0p = (__half*)tb.C + (long long)row0 * ldc;
                __half* r1p = (__half*)tb.C + (long long)(row0 + 8) * ldc;
                st_perm_h2(r0p, col, v00, v01);
                st_perm_h2(r1p, col, v10, v11);
            } else {
                float* Cf = (float*)tb.C;
                *reinterpret_cast<float2*>(&Cf[(long long)row0 * ldc + col]) =
                    make_float2(v00, v01);
                *reinterpret_cast<float2*>(&Cf[(long long)(row0 + 8) * ldc + col]) =
                    make_float2(v10, v11);
            }
        }
    }
}

// ======================================================================
// QK^T fp16: per (b,h): S = Q @ K^T * 0.125.  K-dim = 64 = single tile.
// ======================================================================
__global__ void __launch_bounds__(256, 3) qk_kernel(
    const __half* __restrict__ q, const __half* __restrict__ k, float* __restrict__ P)
{
    extern __shared__ char smc[];
    char* sA = smc;
    char* sB = smc + ABYT;

    int z = blockIdx.z, b = z >> 3, h = z & 7;
    int tid = threadIdx.x, w = tid >> 5, lane = tid & 31;
    int g = lane >> 2, tig = lane & 3;
    int bm = blockIdx.y * 128, bn = blockIdx.x * 64;
    int wm = (w & 3) * 32, wn = (w >> 2) * 32;

    unsigned uA = (unsigned)__cvta_generic_to_shared(sA);
    unsigned uB = (unsigned)__cvta_generic_to_shared(sB);
    int crow = tid >> 3, cch = tid & 7;
    unsigned cxor = (unsigned)((cch * 16) ^ ((crow & 1) << 6));

    #pragma unroll
    for (int i = 0; i < 4; i++)
        CP16(uA + (unsigned)((crow + i * 32) * 128) + cxor,
             q + (long long)(b * T_ + bm + crow + i * 32) * D_ + h * DK_ + cch * 8);
    #pragma unroll
    for (int i = 0; i < 2; i++)
        CP16(uB + (unsigned)((crow + i * 32) * 128) + cxor,
             k + (long long)(b * T_ + bn + crow + i * 32) * D_ + h * DK_ + cch * 8);
    CPCOMMIT();

    float acc[2][4][4];
    #pragma unroll
    for (int i = 0; i < 2; i++)
        #pragma unroll
        for (int j = 0; j < 4; j++)
            #pragma unroll
            for (int qq = 0; qq < 4; qq++) acc[i][j][qq] = 0.f;

    CPWAIT(0);
    __syncthreads();
    MMA_SUB(sA, sB, 0)
    MMA_SUB(sA, sB, 1)

    float* C = P + (long long)z * T_ * T_;
    #pragma unroll
    for (int mt = 0; mt < 2; mt++)
        #pragma unroll
        for (int nt = 0; nt < 4; nt++) {
            int row0 = bm + wm + mt * 16 + g;
            int col  = bn + wn + nt * 8 + 2 * tig;
            *reinterpret_cast<float2*>(&C[(long long)row0 * T_ + col]) =
                make_float2(acc[mt][nt][0] * 0.125f, acc[mt][nt][1] * 0.125f);
            *reinterpret_cast<float2*>(&C[(long long)(row0 + 8) * T_ + col]) =
                make_float2(acc[mt][nt][2] * 0.125f, acc[mt][nt][3] * 0.125f);
        }
}

// ======================================================================
// PV fp16: per (b,h): O[t, dh] = P @ V.  K = 256 tokens (4 tiles of 64).
// P half perm, pitch 512h. vT half perm [512, 8192]. Out half perm.
// ======================================================================
__global__ void __launch_bounds__(256, 2) pv_kernel(
    const __half* __restrict__ Ph, const __half* __restrict__ vT, __half* __restrict__ O)
{
    extern __shared__ char smc[];
    char* sA = smc;
    char* sB = smc + NSTG * ABYT;

    int z = blockIdx.z, b = z >> 3, h = z & 7;
    int tid = threadIdx.x, w = tid >> 5, lane = tid & 31;
    int g = lane >> 2, tig = lane & 3;
    int bm = blockIdx.y * 128;
    int wm = (w & 3) * 32, wn = (w >> 2) * 32;

    unsigned uA = (unsigned)__cvta_generic_to_shared(sA);
    unsigned uB = (unsigned)__cvta_generic_to_shared(sB);
    int crow = tid >> 3, cch = tid & 7;
    unsigned cxor = (unsigned)((cch * 16) ^ ((crow & 1) << 6));

    const __half* aP[4]; const __half* bP[2];
    unsigned dA[4], dB[2];
    #pragma unroll
    for (int i = 0; i < 4; i++) {
        aP[i] = Ph + ((long long)(z * T_ + bm + crow + i * 32)) * 512 + cch * 8;
        dA[i] = uA + (unsigned)((crow + i * 32) * 128) + cxor;
    }
    #pragma unroll
    for (int i = 0; i < 2; i++) {
        bP[i] = vT + (long long)(h * DK_ + crow + i * 32) * (B_ * T_) + b * T_ + cch * 8;
        dB[i] = uB + (unsigned)((crow + i * 32) * 128) + cxor;
    }

    float acc[2][4][4];
    #pragma unroll
    for (int i = 0; i < 2; i++)
        #pragma unroll
        for (int j = 0; j < 4; j++)
            #pragma unroll
            for (int q = 0; q < 4; q++) acc[i][j][q] = 0.f;

    #pragma unroll
    for (int s = 0; s < 3; s++) {
        #pragma unroll
        for (int i = 0; i < 4; i++) CP16(dA[i] + (unsigned)(s * ABYT), aP[i] + s * 64);
        #pragma unroll
        for (int i = 0; i < 2; i++) CP16(dB[i] + (unsigned)(s * BBYT), bP[i] + s * 64);
        CPCOMMIT();
    }

    const int NKT = T_ / 64;   // 4
    for (int kt = 0; kt < NKT; kt++) {
        CPWAIT(2);
        __syncthreads();
        int s = kt & 3;
        char* pA = sA + s * ABYT;
        char* pB = sB + s * BBYT;
        if (kt + 3 < NKT) {
            int rs = (kt + 3) & 3;
            int ko = (kt + 3) * 64;
            #pragma unroll
            for (int i = 0; i < 4; i++) CP16(dA[i] + (unsigned)(rs * ABYT), aP[i] + ko);
            #pragma unroll
            for (int i = 0; i < 2; i++) CP16(dB[i] + (unsigned)(rs * BBYT), bP[i] + ko);
        }
        CPCOMMIT();
        MMA_SUB(pA, pB, 0)
        MMA_SUB(pA, pB, 1)
    }

    #pragma unroll
    for (int mt = 0; mt < 2; mt++)
        #pragma unroll
        for (int nt = 0; nt < 4; nt++) {
            int gr   = b * T_ + bm + wm + mt * 16 + g;
            int colg = h * DK_ + wn + nt * 8 + 2 * tig;
            st_perm_h2(O + (long long)gr * D_, colg, acc[mt][nt][0], acc[mt][nt][1]);
            st_perm_h2(O + (long long)(gr + 8) * D_, colg, acc[mt][nt][2], acc[mt][nt][3]);
        }
}

// ---------------- PVAM head: 5 query positions per block ----------------
__global__ void __launch_bounds__(256) pvam_kernel(
    const float* __restrict__ wf, const float* __restrict__ emb,
    const int* __restrict__ gwp, const float* __restrict__ fc1,
    float* __restrict__ out)
{
    __shared__ float s_wp[5][D_];
    __shared__ float s_f[D_];
    __shared__ float s_sc[5][T_];
    __shared__ float s_red[40];
    int mg = blockIdx.x * 5, b = blockIdx.y;
    int tid = threadIdx.x;
    for (int i = tid; i < 5 * D_; i += 256) {
        int j = i >> 9, c = i & (D_ - 1);
        s_wp[j][c] = emb[(long long)gwp[mg + j] * D_ + c];
    }
    for (int i = tid; i < D_; i += 256) s_f[i] = fc1[i];
    __syncthreads();

    const float* wr = wf + ((long long)b * T_ + tid) * D_;
    float sc[5] = {0.f, 0.f, 0.f, 0.f, 0.f};
    for (int c4 = 0; c4 < D_ / 4; c4++) {
        float4 wv = *reinterpret_cast<const float4*>(&wr[c4 * 4]);
        float4 fv = *reinterpret_cast<const float4*>(&s_f[c4 * 4]);
        #pragma unroll
        for (int j = 0; j < 5; j++) {
            float4 pv = *reinterpret_cast<const float4*>(&s_wp[j][c4 * 4]);
            sc[j] += tanh_fast(wv.x + pv.x) * fv.x;
            sc[j] += tanh_fast(wv.y + pv.y) * fv.y;
            sc[j] += tanh_fast(wv.z + pv.z) * fv.z;
            sc[j] += tanh_fast(wv.w + pv.w) * fv.w;
        }
    }

    int wid = tid >> 5, lane = tid & 31;
    #pragma unroll
    for (int j = 0; j < 5; j++) {
        float mv = sc[j];
        #pragma unroll
        for (int o = 16; o; o >>= 1) mv = fmaxf(mv, __shfl_xor_sync(0xffffffffu, mv, o));
        if (lane == 0) s_red[wid] = mv;
        __syncthreads();
        if (tid < 32) {
            float t = (tid < 8) ? s_red[tid] : -3.0e38f;
            #pragma unroll
            for (int o = 4; o; o >>= 1) t = fmaxf(t, __shfl_xor_sync(0xffffffffu, t, o));
            if (tid == 0) s_red[32] = t;
        }
        __syncthreads();
        float e = __expf(sc[j] - s_red[32]);
        float sv = e;
        #pragma unroll
        for (int o = 16; o; o >>= 1) sv += __shfl_xor_sync(0xffffffffu, sv, o);
        if (lane == 0) s_red[8 + wid] = sv;
        __syncthreads();
        if (tid < 32) {
            float t = (tid < 8) ? s_red[8 + tid] : 0.f;
            #pragma unroll
            for (int o = 4; o; o >>= 1) t += __shfl_xor_sync(0xffffffffu, t, o);
            if (tid == 0) s_red[33] = t;
        }
        __syncthreads();
        s_sc[j][tid] = e * (1.0f / s_red[33]);
        __syncthreads();
    }

    const float* base = wf + (long long)b * T_ * D_;
    int c0 = tid, c1 = tid + 256;
    float a0[5] = {0.f, 0.f, 0.f, 0.f, 0.f};
    float a1[5] = {0.f, 0.f, 0.f, 0.f, 0.f};
    #pragma unroll 4
    for (int t = 0; t < T_; t++) {
        float w0 = base[(long long)t * D_ + c0];
        float w1 = base[(long long)t * D_ + c1];
        #pragma unroll
        for (int j = 0; j < 5; j++) {
            float s = s_sc[j][t];
            a0[j] += s * w0;
            a1[j] += s * w1;
        }
    }
    #pragma unroll
    for (int j = 0; j < 5; j++) {
        long long ob = ((long long)b * ML_ + mg + j) * D_;
        out[ob + c0] = a0[j];
        out[ob + c1] = a1[j];
    }
}

// ---------------- host launcher ----------------
extern "C" void kernel_launch(void* const* d_in, const int* in_sizes, int n_in,
                              void* d_out, int out_size)
{
    const float* x    = (const float*)d_in[0];
    const int*   ewp  = (const int*)  d_in[1];
    const int*   gwp  = (const int*)  d_in[2];
    const float* pos  = (const float*)d_in[3];
    const float* ln1s = (const float*)d_in[4];
    const float* ln1b = (const float*)d_in[5];
    const float* Wq   = (const float*)d_in[6];
    const float* bq   = (const float*)d_in[7];
    const float* Wk   = (const float*)d_in[8];
    const float* bk   = (const float*)d_in[9];
    const float* Wv   = (const float*)d_in[10];
    const float* bv   = (const float*)d_in[11];
    const float* Wo   = (const float*)d_in[12];
    const float* bo   = (const float*)d_in[13];
    const float* ln2s = (const float*)d_in[14];
    const float* ln2b = (const float*)d_in[15];
    const float* W1   = (const float*)d_in[16];
    const float* b1   = (const float*)d_in[17];
    const float* W2   = (const float*)d_in[18];
    const float* b2   = (const float*)d_in[19];
    const float* lnfs = (const float*)d_in[20];
    const float* lnfb = (const float*)d_in[21];
    const float* fc0w = (const float*)d_in[22];
    const float* fc0b = (const float*)d_in[23];
    const float* emb  = (const float*)d_in[24];
    const float* fc1  = (const float*)d_in[25];

    static float *enc = nullptr, *tmp, *q, *k, *v, *o, *p, *wT;
    if (!enc) {
        cudaGetSymbolAddress((void**)&enc, g_enc);
        cudaGetSymbolAddress((void**)&tmp, g_tmp);
        cudaGetSymbolAddress((void**)&q,   g_q);
        cudaGetSymbolAddress((void**)&k,   g_k);
        cudaGetSymbolAddress((void**)&v,   g_v);
        cudaGetSymbolAddress((void**)&o,   g_o);
        cudaGetSymbolAddress((void**)&p,   g_p);
        cudaGetSymbolAddress((void**)&wT,  g_wT);
        cudaFuncSetAttribute(tgemm_kernel,
                             cudaFuncAttributeMaxDynamicSharedMemorySize, TG_SMEM);
        cudaFuncSetAttribute(qk_kernel,
                             cudaFuncAttributeMaxDynamicSharedMemorySize, QK_SMEM);
        cudaFuncSetAttribute(pv_kernel,
                             cudaFuncAttributeMaxDynamicSharedMemorySize, TG_SMEM);
    }

    __half* tmp_h = (__half*)tmp;
    __half* q_h   = (__half*)q;
    __half* k_h   = (__half*)k;
    __half* v_h   = (__half*)v;
    __half* o_h   = (__half*)o;
    __half* p_h   = (__half*)p;
    __half* wT_h  = (__half*)wT;

    const long long DD = (long long)D_ * D_;

    WP wp;
    wp.w[0]  = Wq;       wp.w[1]  = Wk;       wp.w[2]  = Wv;
    wp.w[3]  = Wo;       wp.w[4]  = W1;       wp.w[5]  = W2;
    wp.w[6]  = Wq + DD;  wp.w[7]  = Wk + DD;  wp.w[8]  = Wv + DD;
    wp.w[9]  = Wo + DD;  wp.w[10] = W1 + DD;  wp.w[11] = W2 + DD;
    wp.w[12] = fc0w;
    wtrans_kernel<<<dim3(16, 16, NWMAT), dim3(32, 8)>>>(wp, wT_h);

    prep_kernel<<<dim3(D_ / 32, T_ / 32, B_), dim3(32, 8)>>>(x, pos, ewp, enc);

    const int MT = B_ * T_;                  // 8192
    const dim3 tg1(D_ / 64, MT / 128, 1);    // (8, 64)
    const dim3 tg2(D_ / 64, MT / 128, 2);
    const dim3 tgv(MT / 64, D_ / 128, 1);    // (128, 4) for V^T

    for (int l = 0; l < L_; l++) {
        int vo = l * D_;
        const __half* wq = wT_h + (l * 6 + 0) * DD;
        const __half* wk = wT_h + (l * 6 + 1) * DD;
        const __half* wv = wT_h + (l * 6 + 2) * DD;
        const __half* wo = wT_h + (l * 6 + 3) * DD;
        const __half* w1 = wT_h + (l * 6 + 4) * DD;
        const __half* w2 = wT_h + (l * 6 + 5) * DD;

        ln_kernel<<<MT / 8, dim3(32, 8)>>>(enc, tmp_h, ln1s + vo, ln1b + vo);

        TGArgs aqk;
        aqk.t[0] = {wq, q_h, bq + vo, nullptr, 2, D_};
        aqk.t[1] = {wk, k_h, bk + vo, nullptr, 2, D_};
        tgemm_kernel<<<tg2, 256, TG_SMEM>>>(tmp_h, aqk);

        // V^T[512, 8192] = Wv @ tmp^T (per-row bias, half perm out)
        TGArgs av;
        av.t[0] = {tmp_h, v_h, bv + vo, nullptr, 2 | 4, MT};
        tgemm_kernel<<<tgv, 256, TG_SMEM>>>(wv, av);

        qk_kernel<<<dim3(T_ / 64, T_ / 128, B_ * NH_), 256, QK_SMEM>>>(q_h, k_h, p);
        softmax_kernel<<<(B_ * NH_ * T_) / 8, dim3(32, 8)>>>(p);
        pv_kernel<<<dim3(1, T_ / 128, B_ * NH_), 256, TG_SMEM>>>(p_h, v_h, o_h);

        TGArgs ao; ao.t[0] = {wo, enc, bo + vo, enc, 0, D_};
        tgemm_kernel<<<tg1, 256, TG_SMEM>>>(o_h, ao);

        ln_kernel<<<MT / 8, dim3(32, 8)>>>(enc, tmp_h, ln2s + vo, ln2b + vo);
        TGArgs a1; a1.t[0] = {w1, o_h, b1 + vo, nullptr, 3, D_};
        tgemm_kernel<<<tg1, 256, TG_SMEM>>>(tmp_h, a1);
        TGArgs a2; a2.t[0] = {w2, enc, b2 + vo, enc, 0, D_};
        tgemm_kernel<<<tg1, 256, TG_SMEM>>>(o_h, a2);
    }

    ln_kernel<<<MT / 8, dim3(32, 8)>>>(enc, tmp_h, lnfs, lnfb);
    TGArgs af; af.t[0] = {wT_h + 12 * DD, q, fc0b, nullptr, 0, D_};
    tgemm_kernel<<<tg1, 256, TG_SMEM>>>(tmp_h, af);

    pvam_kernel<<<dim3(ML_ / 5, B_), 256>>>(q, emb, gwp, fc1, (float*)d_out);
}

// round 8
// speedup vs baseline: 2.2186x; 1.0128x over previous
#include <cuda_runtime.h>
#include <cuda_fp16.h>
#include <math.h>

// ---------------- problem constants ----------------
#define B_  32
#define T_  256
#define D_  512
#define NH_ 8
#define DK_ 64
#define L_  2
#define ML_ 25
#define NWMAT 13

// ---------------- scratch ----------------
__device__ float g_enc[B_*T_*D_];
__device__ float g_tmp[B_*T_*D_];
__device__ float g_q  [B_*T_*D_];
__device__ float g_k  [B_*T_*D_];
__device__ float g_v  [B_*T_*D_];   // V^T halves [512, 8192]
__device__ float g_o  [B_*T_*D_];
__device__ float g_p  [B_*NH_*T_*T_];  // P halves, pitch 256
__device__ float g_wT [NWMAT*D_*D_];   // halves, perm layout

__device__ __forceinline__ float tanh_fast(float x) {
    float y;
    asm("tanh.approx.f32 %0, %1;" : "=f"(y) : "f"(x));
    return y;
}
// fp16 fragment k-permutation within a 32-block
__device__ __forceinline__ int pidx32(int k) {
    return ((k & 6) >> 1) * 8 + ((k >> 4) & 1) * 4 + ((k >> 3) & 1) * 2 + (k & 1);
}
__device__ __forceinline__ void st_perm_h2(__half* rowp, int c, float v0, float v1) {
    *reinterpret_cast<__half2*>(&rowp[(c & ~31) + pidx32(c & 31)]) = __floats2half2_rn(v0, v1);
}

#define CP16(dst, src) \
    asm volatile("cp.async.cg.shared.global [%0], [%1], 16;" :: "r"(dst), "l"(src) : "memory")
#define CPCOMMIT() asm volatile("cp.async.commit_group;" ::: "memory")
#define CPWAIT(n)  asm volatile("cp.async.wait_group %0;" :: "n"(n) : "memory")

__device__ __forceinline__ void mma_f16(float c[4],
                                        unsigned a0, unsigned a1, unsigned a2, unsigned a3,
                                        unsigned b0, unsigned b1)
{
    asm volatile(
        "mma.sync.aligned.m16n8k16.row.col.f32.f16.f16.f32 "
        "{%0,%1,%2,%3}, {%4,%5,%6,%7}, {%8,%9}, {%0,%1,%2,%3};"
        : "+f"(c[0]), "+f"(c[1]), "+f"(c[2]), "+f"(c[3])
        : "r"(a0), "r"(a1), "r"(a2), "r"(a3), "r"(b0), "r"(b1));
}

// ---------------- tiling ----------------
#define ABYT 16384
#define BBYT 8192
#define NSTG 4
#define TG_SMEM (NSTG * (ABYT + BBYT))   // 98304

#define MMA_SUB(stgA, stgB, s32) {                                                    \
    uint4 aU[4], bU[4];                                                               \
    _Pragma("unroll")                                                                 \
    for (int r2 = 0; r2 < 4; r2++) {                                                  \
        int row = wm + r2 * 8 + g;                                                    \
        aU[r2] = *reinterpret_cast<const uint4*>(                                     \
            (stgA) + row * 128 + ((((s32) * 64 + tig * 16)) ^ ((row & 1) << 6)));     \
        int rob = wn + r2 * 8 + g;                                                    \
        bU[r2] = *reinterpret_cast<const uint4*>(                                     \
            (stgB) + rob * 128 + ((((s32) * 64 + tig * 16)) ^ ((rob & 1) << 6)));     \
    }                                                                                 \
    _Pragma("unroll")                                                                 \
    for (int mt = 0; mt < 2; mt++)                                                    \
        _Pragma("unroll")                                                             \
        for (int nt = 0; nt < 4; nt++) {                                              \
            mma_f16(acc[mt][nt], aU[2*mt].x, aU[2*mt+1].x, aU[2*mt].y, aU[2*mt+1].y,  \
                    bU[nt].x, bU[nt].y);                                              \
            mma_f16(acc[mt][nt], aU[2*mt].z, aU[2*mt+1].z, aU[2*mt].w, aU[2*mt+1].w,  \
                    bU[nt].z, bU[nt].w);                                              \
        }                                                                             \
}

// ---------------- prep ----------------
__global__ void prep_kernel(const float* __restrict__ x, const float* __restrict__ pos,
                            const int* __restrict__ ewp, float* __restrict__ enc)
{
    __shared__ float tile[32][33];
    int b  = blockIdx.z;
    int d0 = blockIdx.x * 32, t0 = blockIdx.y * 32;
    int tx = threadIdx.x, ty = threadIdx.y;
    const float* xb = x + (long long)b * D_ * T_;
    #pragma unroll
    for (int i = 0; i < 4; i++) {
        int d = ty + i * 8;
        tile[d][tx] = xb[(long long)(d0 + d) * T_ + t0 + tx];
    }
    __syncthreads();
    #pragma unroll
    for (int i = 0; i < 4; i++) {
        int tl = ty + i * 8;
        int t = t0 + tl, d = d0 + tx;
        int pr = ewp[t];
        enc[(((long long)b * T_) + t) * D_ + d] =
            tile[tx][tl] * 22.62741699796952f + pos[(long long)pr * D_ + d];
    }
}

// ---------------- weight transpose -> half perm ----------------
struct WP { const float* w[NWMAT]; };
__global__ void wtrans_kernel(WP p, __half* __restrict__ out)
{
    __shared__ float t[32][33];
    int mi = blockIdx.z;
    const float* W = p.w[mi];
    __half* O = out + (long long)mi * D_ * D_;
    int n0 = blockIdx.x * 32, k0 = blockIdx.y * 32;
    int tx = threadIdx.x, ty = threadIdx.y;
    #pragma unroll
    for (int i = 0; i < 4; i++) {
        int k = k0 + ty + i * 8;
        t[ty + i * 8][tx] = W[(long long)k * D_ + n0 + tx];
    }
    __syncthreads();
    #pragma unroll
    for (int i = 0; i < 4; i++) {
        int n = n0 + ty + i * 8;
        O[(long long)n * D_ + k0 + pidx32(tx)] = __float2half(t[tx][ty + i * 8]);
    }
}

// ---------------- layernorm -> half perm ----------------
__global__ void ln_kernel(const float* __restrict__ in, __half* __restrict__ out,
                          const float* __restrict__ gs, const float* __restrict__ gb)
{
    int row  = blockIdx.x * 8 + threadIdx.y;
    int lane = threadIdx.x;
    const float* r = in + (long long)row * D_;
    float4 xv[4];
    #pragma unroll
    for (int j = 0; j < 4; j++)
        xv[j] = *reinterpret_cast<const float4*>(&r[(j * 32 + lane) * 4]);
    float s = 0.f;
    #pragma unroll
    for (int j = 0; j < 4; j++) s += xv[j].x + xv[j].y + xv[j].z + xv[j].w;
    #pragma unroll
    for (int o = 16; o; o >>= 1) s += __shfl_xor_sync(0xffffffffu, s, o);
    float mean = s * (1.0f / D_);
    float vs = 0.f;
    #pragma unroll
    for (int j = 0; j < 4; j++) {
        float a = xv[j].x - mean, b2 = xv[j].y - mean, c = xv[j].z - mean, d = xv[j].w - mean;
        vs += a * a + b2 * b2 + c * c + d * d;
    }
    #pragma unroll
    for (int o = 16; o; o >>= 1) vs += __shfl_xor_sync(0xffffffffu, vs, o);
    float rstd = rsqrtf(vs * (1.0f / D_) + 1e-5f);
    __half* w = out + (long long)row * D_;
    #pragma unroll
    for (int j = 0; j < 4; j++) {
        int c0 = (j * 32 + lane) * 4;
        float4 sv = *reinterpret_cast<const float4*>(&gs[c0]);
        float4 bv = *reinterpret_cast<const float4*>(&gb[c0]);
        float tx = (xv[j].x - mean) * rstd * sv.x + bv.x;
        float ty = (xv[j].y - mean) * rstd * sv.y + bv.y;
        float tz = (xv[j].z - mean) * rstd * sv.z + bv.z;
        float tw = (xv[j].w - mean) * rstd * sv.w + bv.w;
        st_perm_h2(w, c0,     tx, ty);
        st_perm_h2(w, c0 + 2, tz, tw);
    }
}

// ======================================================================
// fp16 MMA GEMM: per-z (A, Bt, C). CTA 128x64. flags: b0 relu, b1 half-perm
// out, b2 bias-per-row. bxShift decodes blockIdx.x into (bm, bn).
// ======================================================================
struct TGB { const __half* A; const __half* Bt; void* C; const float* bias;
             const float* resid; int flags; int ldc; int bxShift; };
struct TGArgs { TGB t[3]; };

__global__ void __launch_bounds__(256, 2) tgemm_kernel(TGArgs args)
{
    extern __shared__ char smc[];
    char* sA = smc;
    char* sB = smc + NSTG * ABYT;
    TGB tb = args.t[blockIdx.z];

    int tid = threadIdx.x, w = tid >> 5, lane = tid & 31;
    int g = lane >> 2, tig = lane & 3;
    int bx = blockIdx.x;
    int bn = (bx & ((1 << tb.bxShift) - 1)) * 64;
    int bm = (bx >> tb.bxShift) * 128;
    int wm = (w & 3) * 32, wn = (w >> 2) * 32;

    unsigned uA = (unsigned)__cvta_generic_to_shared(sA);
    unsigned uB = (unsigned)__cvta_generic_to_shared(sB);
    int crow = tid >> 3, cch = tid & 7;
    unsigned cxor = (unsigned)((cch * 16) ^ ((crow & 1) << 6));

    const __half* aP[4]; const __half* bP[2];
    unsigned dA[4], dB[2];
    #pragma unroll
    for (int i = 0; i < 4; i++) {
        aP[i] = tb.A + (long long)(bm + crow + i * 32) * D_ + cch * 8;
        dA[i] = uA + (unsigned)((crow + i * 32) * 128) + cxor;
    }
    #pragma unroll
    for (int i = 0; i < 2; i++) {
        bP[i] = tb.Bt + (long long)(bn + crow + i * 32) * D_ + cch * 8;
        dB[i] = uB + (unsigned)((crow + i * 32) * 128) + cxor;
    }

    float acc[2][4][4];
    #pragma unroll
    for (int i = 0; i < 2; i++)
        #pragma unroll
        for (int j = 0; j < 4; j++)
            #pragma unroll
            for (int q = 0; q < 4; q++) acc[i][j][q] = 0.f;

    #pragma unroll
    for (int s = 0; s < 3; s++) {
        #pragma unroll
        for (int i = 0; i < 4; i++) CP16(dA[i] + (unsigned)(s * ABYT), aP[i] + s * 64);
        #pragma unroll
        for (int i = 0; i < 2; i++) CP16(dB[i] + (unsigned)(s * BBYT), bP[i] + s * 64);
        CPCOMMIT();
    }

    const int NKT = D_ / 64;   // 8
    for (int kt = 0; kt < NKT; kt++) {
        CPWAIT(2);
        __syncthreads();
        int s = kt & 3;
        char* pA = sA + s * ABYT;
        char* pB = sB + s * BBYT;
        if (kt + 3 < NKT) {
            int rs = (kt + 3) & 3;
            int ko = (kt + 3) * 64;
            #pragma unroll
            for (int i = 0; i < 4; i++) CP16(dA[i] + (unsigned)(rs * ABYT), aP[i] + ko);
            #pragma unroll
            for (int i = 0; i < 2; i++) CP16(dB[i] + (unsigned)(rs * BBYT), bP[i] + ko);
        }
        CPCOMMIT();
        MMA_SUB(pA, pB, 0)
        MMA_SUB(pA, pB, 1)
    }

    int flags = tb.flags, ldc = tb.ldc;
    #pragma unroll
    for (int mt = 0; mt < 2; mt++) {
        #pragma unroll
        for (int nt = 0; nt < 4; nt++) {
            int row0 = bm + wm + mt * 16 + g;
            int col  = bn + wn + nt * 8 + 2 * tig;
            float v00 = acc[mt][nt][0], v01 = acc[mt][nt][1];
            float v10 = acc[mt][nt][2], v11 = acc[mt][nt][3];
            if (flags & 4) {
                float b0 = tb.bias[row0], b1 = tb.bias[row0 + 8];
                v00 += b0; v01 += b0; v10 += b1; v11 += b1;
            } else {
                float2 bv = *reinterpret_cast<const float2*>(&tb.bias[col]);
                v00 += bv.x; v01 += bv.y; v10 += bv.x; v11 += bv.y;
            }
            if (flags & 1) {
                v00 = fmaxf(v00, 0.f); v01 = fmaxf(v01, 0.f);
                v10 = fmaxf(v10, 0.f); v11 = fmaxf(v11, 0.f);
            }
            if (tb.resid) {
                float2 r0 = *reinterpret_cast<const float2*>(
                    &tb.resid[(long long)row0 * ldc + col]);
                float2 r1 = *reinterpret_cast<const float2*>(
                    &tb.resid[(long long)(row0 + 8) * ldc + col]);
                v00 += r0.x; v01 += r0.y; v10 += r1.x; v11 += r1.y;
            }
            if (flags & 2) {
                __half* r0p = (__half*)tb.C + (long long)row0 * ldc;
                __half* r1p = (__half*)tb.C + (long long)(row0 + 8) * ldc;
                st_perm_h2(r0p, col, v00, v01);
                st_perm_h2(r1p, col, v10, v11);
            } else {
                float* Cf = (float*)tb.C;
                *reinterpret_cast<float2*>(&Cf[(long long)row0 * ldc + col]) =
                    make_float2(v00, v01);
                *reinterpret_cast<float2*>(&Cf[(long long)(row0 + 8) * ldc + col]) =
                    make_float2(v10, v11);
            }
        }
    }
}

// ======================================================================
// Fused QK^T + softmax: CTA = 32 q-rows x ALL 256 key cols, per (b,h).
// Output P half perm, pitch 256. 8 warps of 32x32, K=64 single load.
// ======================================================================
__global__ void __launch_bounds__(256, 2) qk_softmax_kernel(
    const __half* __restrict__ q, const __half* __restrict__ k, __half* __restrict__ P)
{
    __shared__ __align__(16) char sA[4096];    // 32 x 128B
    __shared__ __align__(16) char sB[32768];   // 256 x 128B
    __shared__ float sred[32][8];

    int z = blockIdx.z, b = z >> 3, h = z & 7;
    int bm = blockIdx.x * 32;
    int tid = threadIdx.x, w = tid >> 5, lane = tid & 31;
    int g = lane >> 2, tig = lane & 3;
    int wm = 0, wn = w * 32;

    unsigned uA = (unsigned)__cvta_generic_to_shared(sA);
    unsigned uB = (unsigned)__cvta_generic_to_shared(sB);

    {   // A: 1 cp per thread; B: 8 per thread
        int row = tid >> 3, ch = tid & 7;
        unsigned cx = (unsigned)((ch * 16) ^ ((row & 1) << 6));
        CP16(uA + (unsigned)(row * 128) + cx,
             q + (long long)(b * T_ + bm + row) * D_ + h * DK_ + ch * 8);
        #pragma unroll
        for (int i = 0; i < 8; i++) {
            int idx = tid + i * 256;
            int br = idx >> 3, bch = idx & 7;
            unsigned bx2 = (unsigned)((bch * 16) ^ ((br & 1) << 6));
            CP16(uB + (unsigned)(br * 128) + bx2,
                 k + (long long)(b * T_ + br) * D_ + h * DK_ + bch * 8);
        }
    }
    CPCOMMIT();

    float acc[2][4][4];
    #pragma unroll
    for (int i = 0; i < 2; i++)
        #pragma unroll
        for (int j = 0; j < 4; j++)
            #pragma unroll
            for (int qq = 0; qq < 4; qq++) acc[i][j][qq] = 0.f;

    CPWAIT(0);
    __syncthreads();
    MMA_SUB(sA, sB, 0)
    MMA_SUB(sA, sB, 1)

    // scale
    #pragma unroll
    for (int i = 0; i < 2; i++)
        #pragma unroll
        for (int j = 0; j < 4; j++)
            #pragma unroll
            for (int qq = 0; qq < 4; qq++) acc[i][j][qq] *= 0.125f;

    // row-slots: rs -> row = (rs>>1)*16 + (rs&1)*8 + g, values acc[rs>>1][nt][(rs&1)*2 + {0,1}]
    // pass 1: max
    float rmx[4];
    #pragma unroll
    for (int rs = 0; rs < 4; rs++) {
        int mt = rs >> 1, hh = (rs & 1) * 2;
        float m = -3.0e38f;
        #pragma unroll
        for (int nt = 0; nt < 4; nt++)
            m = fmaxf(m, fmaxf(acc[mt][nt][hh], acc[mt][nt][hh + 1]));
        m = fmaxf(m, __shfl_xor_sync(0xffffffffu, m, 1));
        m = fmaxf(m, __shfl_xor_sync(0xffffffffu, m, 2));
        rmx[rs] = m;
        if (tig == 0) sred[mt * 16 + (rs & 1) * 8 + g][w] = m;
    }
    __syncthreads();
    #pragma unroll
    for (int rs = 0; rs < 4; rs++) {
        int rr = (rs >> 1) * 16 + (rs & 1) * 8 + g;
        float m = sred[rr][0];
        #pragma unroll
        for (int ww = 1; ww < 8; ww++) m = fmaxf(m, sred[rr][ww]);
        rmx[rs] = m;
    }
    __syncthreads();
    // pass 2: exp + sum
    float rsum[4];
    #pragma unroll
    for (int rs = 0; rs < 4; rs++) {
        int mt = rs >> 1, hh = (rs & 1) * 2;
        float s = 0.f;
        #pragma unroll
        for (int nt = 0; nt < 4; nt++) {
            float e0 = __expf(acc[mt][nt][hh]     - rmx[rs]);
            float e1 = __expf(acc[mt][nt][hh + 1] - rmx[rs]);
            acc[mt][nt][hh]     = e0;
            acc[mt][nt][hh + 1] = e1;
            s += e0 + e1;
        }
        s += __shfl_xor_sync(0xffffffffu, s, 1);
        s += __shfl_xor_sync(0xffffffffu, s, 2);
        rsum[rs] = s;
        if (tig == 0) sred[mt * 16 + (rs & 1) * 8 + g][w] = s;
    }
    __syncthreads();
    #pragma unroll
    for (int rs = 0; rs < 4; rs++) {
        int rr = (rs >> 1) * 16 + (rs & 1) * 8 + g;
        float s = sred[rr][0];
        #pragma unroll
        for (int ww = 1; ww < 8; ww++) s += sred[rr][ww];
        rsum[rs] = 1.0f / s;
    }

    __half* Pz = P + (long long)z * T_ * T_;
    #pragma unroll
    for (int mt = 0; mt < 2; mt++)
        #pragma unroll
        for (int nt = 0; nt < 4; nt++) {
            int col = wn + nt * 8 + 2 * tig;
            int r0 = bm + mt * 16 + g;
            float i0 = rsum[mt * 2 + 0], i1 = rsum[mt * 2 + 1];
            st_perm_h2(Pz + (long long)r0 * T_, col,
                       acc[mt][nt][0] * i0, acc[mt][nt][1] * i0);
            st_perm_h2(Pz + (long long)(r0 + 8) * T_, col,
                       acc[mt][nt][2] * i1, acc[mt][nt][3] * i1);
        }
}

// ======================================================================
// PV fp16: O[t, dh] = P @ V. P half perm pitch 256; vT half perm [512,8192].
// ======================================================================
__global__ void __launch_bounds__(256, 2) pv_kernel(
    const __half* __restrict__ Ph, const __half* __restrict__ vT, __half* __restrict__ O)
{
    extern __shared__ char smc[];
    char* sA = smc;
    char* sB = smc + NSTG * ABYT;

    int z = blockIdx.z, b = z >> 3, h = z & 7;
    int tid = threadIdx.x, w = tid >> 5, lane = tid & 31;
    int g = lane >> 2, tig = lane & 3;
    int bm = blockIdx.y * 128;
    int wm = (w & 3) * 32, wn = (w >> 2) * 32;

    unsigned uA = (unsigned)__cvta_generic_to_shared(sA);
    unsigned uB = (unsigned)__cvta_generic_to_shared(sB);
    int crow = tid >> 3, cch = tid & 7;
    unsigned cxor = (unsigned)((cch * 16) ^ ((crow & 1) << 6));

    const __half* aP[4]; const __half* bP[2];
    unsigned dA[4], dB[2];
    #pragma unroll
    for (int i = 0; i < 4; i++) {
        aP[i] = Ph + ((long long)z * T_ + bm + crow + i * 32) * T_ + cch * 8;
        dA[i] = uA + (unsigned)((crow + i * 32) * 128) + cxor;
    }
    #pragma unroll
    for (int i = 0; i < 2; i++) {
        bP[i] = vT + (long long)(h * DK_ + crow + i * 32) * (B_ * T_) + b * T_ + cch * 8;
        dB[i] = uB + (unsigned)((crow + i * 32) * 128) + cxor;
    }

    float acc[2][4][4];
    #pragma unroll
    for (int i = 0; i < 2; i++)
        #pragma unroll
        for (int j = 0; j < 4; j++)
            #pragma unroll
            for (int q = 0; q < 4; q++) acc[i][j][q] = 0.f;

    #pragma unroll
    for (int s = 0; s < 3; s++) {
        #pragma unroll
        for (int i = 0; i < 4; i++) CP16(dA[i] + (unsigned)(s * ABYT), aP[i] + s * 64);
        #pragma unroll
        for (int i = 0; i < 2; i++) CP16(dB[i] + (unsigned)(s * BBYT), bP[i] + s * 64);
        CPCOMMIT();
    }

    const int NKT = T_ / 64;   // 4
    for (int kt = 0; kt < NKT; kt++) {
        CPWAIT(2);
        __syncthreads();
        int s = kt & 3;
        char* pA = sA + s * ABYT;
        char* pB = sB + s * BBYT;
        if (kt + 3 < NKT) {
            int rs = (kt + 3) & 3;
            int ko = (kt + 3) * 64;
            #pragma unroll
            for (int i = 0; i < 4; i++) CP16(dA[i] + (unsigned)(rs * ABYT), aP[i] + ko);
            #pragma unroll
            for (int i = 0; i < 2; i++) CP16(dB[i] + (unsigned)(rs * BBYT), bP[i] + ko);
        }
        CPCOMMIT();
        MMA_SUB(pA, pB, 0)
        MMA_SUB(pA, pB, 1)
    }

    #pragma unroll
    for (int mt = 0; mt < 2; mt++)
        #pragma unroll
        for (int nt = 0; nt < 4; nt++) {
            int gr   = b * T_ + bm + wm + mt * 16 + g;
            int colg = h * DK_ + wn + nt * 8 + 2 * tig;
            st_perm_h2(O + (long long)gr * D_, colg, acc[mt][nt][0], acc[mt][nt][1]);
            st_perm_h2(O + (long long)(gr + 8) * D_, colg, acc[mt][nt][2], acc[mt][nt][3]);
        }
}

// ---------------- PVAM head: 5 query positions per block ----------------
__global__ void __launch_bounds__(256) pvam_kernel(
    const float* __restrict__ wf, const float* __restrict__ emb,
    const int* __restrict__ gwp, const float* __restrict__ fc1,
    float* __restrict__ out)
{
    __shared__ float s_wp[5][D_];
    __shared__ float s_f[D_];
    __shared__ float s_sc[5][T_];
    __shared__ float s_red[40];
    int mg = blockIdx.x * 5, b = blockIdx.y;
    int tid = threadIdx.x;
    for (int i = tid; i < 5 * D_; i += 256) {
        int j = i >> 9, c = i & (D_ - 1);
        s_wp[j][c] = emb[(long long)gwp[mg + j] * D_ + c];
    }
    for (int i = tid; i < D_; i += 256) s_f[i] = fc1[i];
    __syncthreads();

    const float* wr = wf + ((long long)b * T_ + tid) * D_;
    float sc[5] = {0.f, 0.f, 0.f, 0.f, 0.f};
    for (int c4 = 0; c4 < D_ / 4; c4++) {
        float4 wv = *reinterpret_cast<const float4*>(&wr[c4 * 4]);
        float4 fv = *reinterpret_cast<const float4*>(&s_f[c4 * 4]);
        #pragma unroll
        for (int j = 0; j < 5; j++) {
            float4 pv = *reinterpret_cast<const float4*>(&s_wp[j][c4 * 4]);
            sc[j] += tanh_fast(wv.x + pv.x) * fv.x;
            sc[j] += tanh_fast(wv.y + pv.y) * fv.y;
            sc[j] += tanh_fast(wv.z + pv.z) * fv.z;
            sc[j] += tanh_fast(wv.w + pv.w) * fv.w;
        }
    }

    int wid = tid >> 5, lane = tid & 31;
    #pragma unroll
    for (int j = 0; j < 5; j++) {
        float mv = sc[j];
        #pragma unroll
        for (int o = 16; o; o >>= 1) mv = fmaxf(mv, __shfl_xor_sync(0xffffffffu, mv, o));
        if (lane == 0) s_red[wid] = mv;
        __syncthreads();
        if (tid < 32) {
            float t = (tid < 8) ? s_red[tid] : -3.0e38f;
            #pragma unroll
            for (int o = 4; o; o >>= 1) t = fmaxf(t, __shfl_xor_sync(0xffffffffu, t, o));
            if (tid == 0) s_red[32] = t;
        }
        __syncthreads();
        float e = __expf(sc[j] - s_red[32]);
        float sv = e;
        #pragma unroll
        for (int o = 16; o; o >>= 1) sv += __shfl_xor_sync(0xffffffffu, sv, o);
        if (lane == 0) s_red[8 + wid] = sv;
        __syncthreads();
        if (tid < 32) {
            float t = (tid < 8) ? s_red[8 + tid] : 0.f;
            #pragma unroll
            for (int o = 4; o; o >>= 1) t += __shfl_xor_sync(0xffffffffu, t, o);
            if (tid == 0) s_red[33] = t;
        }
        __syncthreads();
        s_sc[j][tid] = e * (1.0f / s_red[33]);
        __syncthreads();
    }

    const float* base = wf + (long long)b * T_ * D_;
    int c0 = tid, c1 = tid + 256;
    float a0[5] = {0.f, 0.f, 0.f, 0.f, 0.f};
    float a1[5] = {0.f, 0.f, 0.f, 0.f, 0.f};
    #pragma unroll 4
    for (int t = 0; t < T_; t++) {
        float w0 = base[(long long)t * D_ + c0];
        float w1 = base[(long long)t * D_ + c1];
        #pragma unroll
        for (int j = 0; j < 5; j++) {
            float s = s_sc[j][t];
            a0[j] += s * w0;
            a1[j] += s * w1;
        }
    }
    #pragma unroll
    for (int j = 0; j < 5; j++) {
        long long ob = ((long long)b * ML_ + mg + j) * D_;
        out[ob + c0] = a0[j];
        out[ob + c1] = a1[j];
    }
}

// ---------------- host launcher ----------------
extern "C" void kernel_launch(void* const* d_in, const int* in_sizes, int n_in,
                              void* d_out, int out_size)
{
    const float* x    = (const float*)d_in[0];
    const int*   ewp  = (const int*)  d_in[1];
    const int*   gwp  = (const int*)  d_in[2];
    const float* pos  = (const float*)d_in[3];
    const float* ln1s = (const float*)d_in[4];
    const float* ln1b = (const float*)d_in[5];
    const float* Wq   = (const float*)d_in[6];
    const float* bq   = (const float*)d_in[7];
    const float* Wk   = (const float*)d_in[8];
    const float* bk   = (const float*)d_in[9];
    const float* Wv   = (const float*)d_in[10];
    const float* bv   = (const float*)d_in[11];
    const float* Wo   = (const float*)d_in[12];
    const float* bo   = (const float*)d_in[13];
    const float* ln2s = (const float*)d_in[14];
    const float* ln2b = (const float*)d_in[15];
    const float* W1   = (const float*)d_in[16];
    const float* b1   = (const float*)d_in[17];
    const float* W2   = (const float*)d_in[18];
    const float* b2   = (const float*)d_in[19];
    const float* lnfs = (const float*)d_in[20];
    const float* lnfb = (const float*)d_in[21];
    const float* fc0w = (const float*)d_in[22];
    const float* fc0b = (const float*)d_in[23];
    const float* emb  = (const float*)d_in[24];
    const float* fc1  = (const float*)d_in[25];

    static float *enc = nullptr, *tmp, *q, *k, *v, *o, *p, *wT;
    if (!enc) {
        cudaGetSymbolAddress((void**)&enc, g_enc);
        cudaGetSymbolAddress((void**)&tmp, g_tmp);
        cudaGetSymbolAddress((void**)&q,   g_q);
        cudaGetSymbolAddress((void**)&k,   g_k);
        cudaGetSymbolAddress((void**)&v,   g_v);
        cudaGetSymbolAddress((void**)&o,   g_o);
        cudaGetSymbolAddress((void**)&p,   g_p);
        cudaGetSymbolAddress((void**)&wT,  g_wT);
        cudaFuncSetAttribute(tgemm_kernel,
                             cudaFuncAttributeMaxDynamicSharedMemorySize, TG_SMEM);
        cudaFuncSetAttribute(pv_kernel,
                             cudaFuncAttributeMaxDynamicSharedMemorySize, TG_SMEM);
    }

    __half* tmp_h = (__half*)tmp;
    __half* q_h   = (__half*)q;
    __half* k_h   = (__half*)k;
    __half* v_h   = (__half*)v;
    __half* o_h   = (__half*)o;
    __half* p_h   = (__half*)p;
    __half* wT_h  = (__half*)wT;

    const long long DD = (long long)D_ * D_;

    WP wp;
    wp.w[0]  = Wq;       wp.w[1]  = Wk;       wp.w[2]  = Wv;
    wp.w[3]  = Wo;       wp.w[4]  = W1;       wp.w[5]  = W2;
    wp.w[6]  = Wq + DD;  wp.w[7]  = Wk + DD;  wp.w[8]  = Wv + DD;
    wp.w[9]  = Wo + DD;  wp.w[10] = W1 + DD;  wp.w[11] = W2 + DD;
    wp.w[12] = fc0w;
    wtrans_kernel<<<dim3(16, 16, NWMAT), dim3(32, 8)>>>(wp, wT_h);

    prep_kernel<<<dim3(D_ / 32, T_ / 32, B_), dim3(32, 8)>>>(x, pos, ewp, enc);

    const int MT = B_ * T_;   // 8192

    for (int l = 0; l < L_; l++) {
        int vo = l * D_;
        const __half* wq = wT_h + (l * 6 + 0) * DD;
        const __half* wk = wT_h + (l * 6 + 1) * DD;
        const __half* wv = wT_h + (l * 6 + 2) * DD;
        const __half* wo = wT_h + (l * 6 + 3) * DD;
        const __half* w1 = wT_h + (l * 6 + 4) * DD;
        const __half* w2 = wT_h + (l * 6 + 5) * DD;

        ln_kernel<<<MT / 8, dim3(32, 8)>>>(enc, tmp_h, ln1s + vo, ln1b + vo);

        // QKV in one launch (Q, K normal; V^T with weights as A)
        TGArgs aqkv;
        aqkv.t[0] = {tmp_h, wq, q_h, bq + vo, nullptr, 2, D_, 3};
        aqkv.t[1] = {tmp_h, wk, k_h, bk + vo, nullptr, 2, D_, 3};
        aqkv.t[2] = {wv, tmp_h, v_h, bv + vo, nullptr, 2 | 4, MT, 7};
        tgemm_kernel<<<dim3(512, 1, 3), 256, TG_SMEM>>>(aqkv);

        qk_softmax_kernel<<<dim3(T_ / 32, 1, B_ * NH_), 256>>>(q_h, k_h, p_h);
        pv_kernel<<<dim3(1, T_ / 128, B_ * NH_), 256, TG_SMEM>>>(p_h, v_h, o_h);

        TGArgs ao; ao.t[0] = {o_h, wo, enc, bo + vo, enc, 0, D_, 3};
        tgemm_kernel<<<dim3(512, 1, 1), 256, TG_SMEM>>>(ao);

        ln_kernel<<<MT / 8, dim3(32, 8)>>>(enc, tmp_h, ln2s + vo, ln2b + vo);
        TGArgs a1; a1.t[0] = {tmp_h, w1, o_h, b1 + vo, nullptr, 3, D_, 3};
        tgemm_kernel<<<dim3(512, 1, 1), 256, TG_SMEM>>>(a1);
        TGArgs a2; a2.t[0] = {o_h, w2, enc, b2 + vo, enc, 0, D_, 3};
        tgemm_kernel<<<dim3(512, 1, 1), 256, TG_SMEM>>>(a2);
    }

    ln_kernel<<<MT / 8, dim3(32, 8)>>>(enc, tmp_h, lnfs, lnfb);
    TGArgs af; af.t[0] = {tmp_h, wT_h + 12 * DD, q, fc0b, nullptr, 0, D_, 3};
    tgemm_kernel<<<dim3(512, 1, 1), 256, TG_SMEM>>>(af);

    pvam_kernel<<<dim3(ML_ / 5, B_), 256>>>(q, emb, gwp, fc1, (float*)d_out);
}

// round 9
// speedup vs baseline: 2.2485x; 1.0135x over previous
#include <cuda_runtime.h>
#include <cuda_fp16.h>
#include <math.h>

// ---------------- problem constants ----------------
#define B_  32
#define T_  256
#define D_  512
#define NH_ 8
#define DK_ 64
#define L_  2
#define ML_ 25
#define NWMAT 13

// ---------------- scratch ----------------
__device__ float g_enc[B_*T_*D_];
__device__ float g_tmp[B_*T_*D_];
__device__ float g_q  [B_*T_*D_];
__device__ float g_k  [B_*T_*D_];
__device__ float g_v  [B_*T_*D_];   // V^T halves [512, 8192]
__device__ float g_o  [B_*T_*D_];
__device__ float g_p  [B_*NH_*T_*T_];  // P halves, pitch 256
__device__ float g_wT [NWMAT*D_*D_];   // halves, perm layout

__device__ __forceinline__ float tanh_fast(float x) {
    float y;
    asm("tanh.approx.f32 %0, %1;" : "=f"(y) : "f"(x));
    return y;
}
__device__ __forceinline__ int pidx32(int k) {
    return ((k & 6) >> 1) * 8 + ((k >> 4) & 1) * 4 + ((k >> 3) & 1) * 2 + (k & 1);
}
__device__ __forceinline__ void st_perm_h2(__half* rowp, int c, float v0, float v1) {
    *reinterpret_cast<__half2*>(&rowp[(c & ~31) + pidx32(c & 31)]) = __floats2half2_rn(v0, v1);
}

#define CP16(dst, src) \
    asm volatile("cp.async.cg.shared.global [%0], [%1], 16;" :: "r"(dst), "l"(src) : "memory")
#define CPCOMMIT() asm volatile("cp.async.commit_group;" ::: "memory")
#define CPWAIT(n)  asm volatile("cp.async.wait_group %0;" :: "n"(n) : "memory")

__device__ __forceinline__ void mma_f16(float c[4],
                                        unsigned a0, unsigned a1, unsigned a2, unsigned a3,
                                        unsigned b0, unsigned b1)
{
    asm volatile(
        "mma.sync.aligned.m16n8k16.row.col.f32.f16.f16.f32 "
        "{%0,%1,%2,%3}, {%4,%5,%6,%7}, {%8,%9}, {%0,%1,%2,%3};"
        : "+f"(c[0]), "+f"(c[1]), "+f"(c[2]), "+f"(c[3])
        : "r"(a0), "r"(a1), "r"(a2), "r"(a3), "r"(b0), "r"(b1));
}

// ---------------- tiling ----------------
#define ABYT 16384
#define BBYT 8192
#define NSTG 4
#define TG_SMEM (NSTG * (ABYT + BBYT))   // 98304

// MMA on one 32-k sub-block using PRECOMPUTED fragment offsets
#define MMA_SUB2(stgA, stgB, AOFF, BOFF) {                                            \
    uint4 aU[4], bU[4];                                                               \
    _Pragma("unroll")                                                                 \
    for (int r2 = 0; r2 < 4; r2++) {                                                  \
        aU[r2] = *reinterpret_cast<const uint4*>((stgA) + (AOFF)[r2]);                \
        bU[r2] = *reinterpret_cast<const uint4*>((stgB) + (BOFF)[r2]);                \
    }                                                                                 \
    _Pragma("unroll")                                                                 \
    for (int mt = 0; mt < 2; mt++)                                                    \
        _Pragma("unroll")                                                             \
        for (int nt = 0; nt < 4; nt++) {                                              \
            mma_f16(acc[mt][nt], aU[2*mt].x, aU[2*mt+1].x, aU[2*mt].y, aU[2*mt+1].y,  \
                    bU[nt].x, bU[nt].y);                                              \
            mma_f16(acc[mt][nt], aU[2*mt].z, aU[2*mt+1].z, aU[2*mt].w, aU[2*mt+1].w,  \
                    bU[nt].z, bU[nt].w);                                              \
        }                                                                             \
}

// precompute fragment offsets: addr(sub) = row*128 + tig*16 + ((row&1)^sub)*64
#define FRAG_OFFSETS()                                                                \
    unsigned paL[4], paH[4], pbL[4], pbH[4];                                          \
    _Pragma("unroll")                                                                 \
    for (int r2 = 0; r2 < 4; r2++) {                                                  \
        int row = wm + r2 * 8 + g;                                                    \
        paL[r2] = (unsigned)(row * 128 + tig * 16 + ((row & 1) << 6));                \
        paH[r2] = paL[r2] ^ 64u;                                                      \
        int rob = wn + r2 * 8 + g;                                                    \
        pbL[r2] = (unsigned)(rob * 128 + tig * 16 + ((rob & 1) << 6));                \
        pbH[r2] = pbL[r2] ^ 64u;                                                      \
    }

// ---------------- prep ----------------
__global__ void prep_kernel(const float* __restrict__ x, const float* __restrict__ pos,
                            const int* __restrict__ ewp, float* __restrict__ enc)
{
    __shared__ float tile[32][33];
    int b  = blockIdx.z;
    int d0 = blockIdx.x * 32, t0 = blockIdx.y * 32;
    int tx = threadIdx.x, ty = threadIdx.y;
    const float* xb = x + (long long)b * D_ * T_;
    #pragma unroll
    for (int i = 0; i < 4; i++) {
        int d = ty + i * 8;
        tile[d][tx] = xb[(long long)(d0 + d) * T_ + t0 + tx];
    }
    __syncthreads();
    #pragma unroll
    for (int i = 0; i < 4; i++) {
        int tl = ty + i * 8;
        int t = t0 + tl, d = d0 + tx;
        int pr = ewp[t];
        enc[(((long long)b * T_) + t) * D_ + d] =
            tile[tx][tl] * 22.62741699796952f + pos[(long long)pr * D_ + d];
    }
}

// ---------------- weight transpose -> half perm ----------------
struct WP { const float* w[NWMAT]; };
__global__ void wtrans_kernel(WP p, __half* __restrict__ out)
{
    __shared__ float t[32][33];
    int mi = blockIdx.z;
    const float* W = p.w[mi];
    __half* O = out + (long long)mi * D_ * D_;
    int n0 = blockIdx.x * 32, k0 = blockIdx.y * 32;
    int tx = threadIdx.x, ty = threadIdx.y;
    #pragma unroll
    for (int i = 0; i < 4; i++) {
        int k = k0 + ty + i * 8;
        t[ty + i * 8][tx] = W[(long long)k * D_ + n0 + tx];
    }
    __syncthreads();
    #pragma unroll
    for (int i = 0; i < 4; i++) {
        int n = n0 + ty + i * 8;
        O[(long long)n * D_ + k0 + pidx32(tx)] = __float2half(t[tx][ty + i * 8]);
    }
}

// ---------------- layernorm -> half perm ----------------
__global__ void ln_kernel(const float* __restrict__ in, __half* __restrict__ out,
                          const float* __restrict__ gs, const float* __restrict__ gb)
{
    int row  = blockIdx.x * 8 + threadIdx.y;
    int lane = threadIdx.x;
    const float* r = in + (long long)row * D_;
    float4 xv[4];
    #pragma unroll
    for (int j = 0; j < 4; j++)
        xv[j] = *reinterpret_cast<const float4*>(&r[(j * 32 + lane) * 4]);
    float s = 0.f;
    #pragma unroll
    for (int j = 0; j < 4; j++) s += xv[j].x + xv[j].y + xv[j].z + xv[j].w;
    #pragma unroll
    for (int o = 16; o; o >>= 1) s += __shfl_xor_sync(0xffffffffu, s, o);
    float mean = s * (1.0f / D_);
    float vs = 0.f;
    #pragma unroll
    for (int j = 0; j < 4; j++) {
        float a = xv[j].x - mean, b2 = xv[j].y - mean, c = xv[j].z - mean, d = xv[j].w - mean;
        vs += a * a + b2 * b2 + c * c + d * d;
    }
    #pragma unroll
    for (int o = 16; o; o >>= 1) vs += __shfl_xor_sync(0xffffffffu, vs, o);
    float rstd = rsqrtf(vs * (1.0f / D_) + 1e-5f);
    __half* w = out + (long long)row * D_;
    #pragma unroll
    for (int j = 0; j < 4; j++) {
        int c0 = (j * 32 + lane) * 4;
        float4 sv = *reinterpret_cast<const float4*>(&gs[c0]);
        float4 bv = *reinterpret_cast<const float4*>(&gb[c0]);
        float tx = (xv[j].x - mean) * rstd * sv.x + bv.x;
        float ty = (xv[j].y - mean) * rstd * sv.y + bv.y;
        float tz = (xv[j].z - mean) * rstd * sv.z + bv.z;
        float tw = (xv[j].w - mean) * rstd * sv.w + bv.w;
        st_perm_h2(w, c0,     tx, ty);
        st_perm_h2(w, c0 + 2, tz, tw);
    }
}

// ======================================================================
// fp16 MMA GEMM: per-z (A, Bt, C). CTA 128x64, fully unrolled K loop.
// ======================================================================
struct TGB { const __half* A; const __half* Bt; void* C; const float* bias;
             const float* resid; int flags; int ldc; int bxShift; };
struct TGArgs { TGB t[3]; };

__global__ void __launch_bounds__(256, 2) tgemm_kernel(TGArgs args)
{
    extern __shared__ char smc[];
    char* sA = smc;
    char* sB = smc + NSTG * ABYT;
    TGB tb = args.t[blockIdx.z];

    int tid = threadIdx.x, w = tid >> 5, lane = tid & 31;
    int g = lane >> 2, tig = lane & 3;
    int bx = blockIdx.x;
    int bn = (bx & ((1 << tb.bxShift) - 1)) * 64;
    int bm = (bx >> tb.bxShift) * 128;
    int wm = (w & 3) * 32, wn = (w >> 2) * 32;

    unsigned uA = (unsigned)__cvta_generic_to_shared(sA);
    unsigned uB = (unsigned)__cvta_generic_to_shared(sB);
    int crow = tid >> 3, cch = tid & 7;
    unsigned cxor = (unsigned)((cch * 16) ^ ((crow & 1) << 6));

    const __half* aP[4]; const __half* bP[2];
    unsigned dA[4], dB[2];
    #pragma unroll
    for (int i = 0; i < 4; i++) {
        aP[i] = tb.A + (long long)(bm + crow + i * 32) * D_ + cch * 8;
        dA[i] = uA + (unsigned)((crow + i * 32) * 128) + cxor;
    }
    #pragma unroll
    for (int i = 0; i < 2; i++) {
        bP[i] = tb.Bt + (long long)(bn + crow + i * 32) * D_ + cch * 8;
        dB[i] = uB + (unsigned)((crow + i * 32) * 128) + cxor;
    }

    FRAG_OFFSETS()

    float acc[2][4][4];
    #pragma unroll
    for (int i = 0; i < 2; i++)
        #pragma unroll
        for (int j = 0; j < 4; j++)
            #pragma unroll
            for (int q = 0; q < 4; q++) acc[i][j][q] = 0.f;

    #pragma unroll
    for (int s = 0; s < 3; s++) {
        #pragma unroll
        for (int i = 0; i < 4; i++) CP16(dA[i] + (unsigned)(s * ABYT), aP[i] + s * 64);
        #pragma unroll
        for (int i = 0; i < 2; i++) CP16(dB[i] + (unsigned)(s * BBYT), bP[i] + s * 64);
        CPCOMMIT();
    }

    const int NKT = D_ / 64;   // 8
    #pragma unroll
    for (int kt = 0; kt < NKT; kt++) {
        CPWAIT(2);
        __syncthreads();
        int s = kt & 3;
        char* pA = sA + s * ABYT;
        char* pB = sB + s * BBYT;
        if (kt + 3 < NKT) {
            int rs = (kt + 3) & 3;
            int ko = (kt + 3) * 64;
            #pragma unroll
            for (int i = 0; i < 4; i++) CP16(dA[i] + (unsigned)(rs * ABYT), aP[i] + ko);
            #pragma unroll
            for (int i = 0; i < 2; i++) CP16(dB[i] + (unsigned)(rs * BBYT), bP[i] + ko);
        }
        CPCOMMIT();
        MMA_SUB2(pA, pB, paL, pbL)
        MMA_SUB2(pA, pB, paH, pbH)
    }

    int flags = tb.flags, ldc = tb.ldc;
    #pragma unroll
    for (int mt = 0; mt < 2; mt++) {
        #pragma unroll
        for (int nt = 0; nt < 4; nt++) {
            int row0 = bm + wm + mt * 16 + g;
            int col  = bn + wn + nt * 8 + 2 * tig;
            float v00 = acc[mt][nt][0], v01 = acc[mt][nt][1];
            float v10 = acc[mt][nt][2], v11 = acc[mt][nt][3];
            if (flags & 4) {
                float b0 = tb.bias[row0], b1 = tb.bias[row0 + 8];
                v00 += b0; v01 += b0; v10 += b1; v11 += b1;
            } else {
                float2 bv = *reinterpret_cast<const float2*>(&tb.bias[col]);
                v00 += bv.x; v01 += bv.y; v10 += bv.x; v11 += bv.y;
            }
            if (flags & 1) {
                v00 = fmaxf(v00, 0.f); v01 = fmaxf(v01, 0.f);
                v10 = fmaxf(v10, 0.f); v11 = fmaxf(v11, 0.f);
            }
            if (tb.resid) {
                float2 r0 = *reinterpret_cast<const float2*>(
                    &tb.resid[(long long)row0 * ldc + col]);
                float2 r1 = *reinterpret_cast<const float2*>(
                    &tb.resid[(long long)(row0 + 8) * ldc + col]);
                v00 += r0.x; v01 += r0.y; v10 += r1.x; v11 += r1.y;
            }
            if (flags & 2) {
                __half* r0p = (__half*)tb.C + (long long)row0 * ldc;
                __half* r1p = (__half*)tb.C + (long long)(row0 + 8) * ldc;
                st_perm_h2(r0p, col, v00, v01);
                st_perm_h2(r1p, col, v10, v11);
            } else {
                float* Cf = (float*)tb.C;
                *reinterpret_cast<float2*>(&Cf[(long long)row0 * ldc + col]) =
                    make_float2(v00, v01);
                *reinterpret_cast<float2*>(&Cf[(long long)(row0 + 8) * ldc + col]) =
                    make_float2(v10, v11);
            }
        }
    }
}

// ======================================================================
// Fused QK^T + softmax: CTA = 32 q-rows x ALL 256 key cols, per (b,h).
// ======================================================================
__global__ void __launch_bounds__(256, 2) qk_softmax_kernel(
    const __half* __restrict__ q, const __half* __restrict__ k, __half* __restrict__ P)
{
    __shared__ __align__(16) char sA[4096];
    __shared__ __align__(16) char sB[32768];
    __shared__ float sred[32][8];

    int z = blockIdx.z, b = z >> 3, h = z & 7;
    int bm = blockIdx.x * 32;
    int tid = threadIdx.x, w = tid >> 5, lane = tid & 31;
    int g = lane >> 2, tig = lane & 3;
    int wm = 0, wn = w * 32;

    unsigned uA = (unsigned)__cvta_generic_to_shared(sA);
    unsigned uB = (unsigned)__cvta_generic_to_shared(sB);

    {
        int row = tid >> 3, ch = tid & 7;
        unsigned cx = (unsigned)((ch * 16) ^ ((row & 1) << 6));
        CP16(uA + (unsigned)(row * 128) + cx,
             q + (long long)(b * T_ + bm + row) * D_ + h * DK_ + ch * 8);
        #pragma unroll
        for (int i = 0; i < 8; i++) {
            int idx = tid + i * 256;
            int br = idx >> 3, bch = idx & 7;
            unsigned bx2 = (unsigned)((bch * 16) ^ ((br & 1) << 6));
            CP16(uB + (unsigned)(br * 128) + bx2,
                 k + (long long)(b * T_ + br) * D_ + h * DK_ + bch * 8);
        }
    }
    CPCOMMIT();

    FRAG_OFFSETS()

    float acc[2][4][4];
    #pragma unroll
    for (int i = 0; i < 2; i++)
        #pragma unroll
        for (int j = 0; j < 4; j++)
            #pragma unroll
            for (int qq = 0; qq < 4; qq++) acc[i][j][qq] = 0.f;

    CPWAIT(0);
    __syncthreads();
    MMA_SUB2(sA, sB, paL, pbL)
    MMA_SUB2(sA, sB, paH, pbH)

    #pragma unroll
    for (int i = 0; i < 2; i++)
        #pragma unroll
        for (int j = 0; j < 4; j++)
            #pragma unroll
            for (int qq = 0; qq < 4; qq++) acc[i][j][qq] *= 0.125f;

    float rmx[4];
    #pragma unroll
    for (int rs = 0; rs < 4; rs++) {
        int mt = rs >> 1, hh = (rs & 1) * 2;
        float m = -3.0e38f;
        #pragma unroll
        for (int nt = 0; nt < 4; nt++)
            m = fmaxf(m, fmaxf(acc[mt][nt][hh], acc[mt][nt][hh + 1]));
        m = fmaxf(m, __shfl_xor_sync(0xffffffffu, m, 1));
        m = fmaxf(m, __shfl_xor_sync(0xffffffffu, m, 2));
        rmx[rs] = m;
        if (tig == 0) sred[mt * 16 + (rs & 1) * 8 + g][w] = m;
    }
    __syncthreads();
    #pragma unroll
    for (int rs = 0; rs < 4; rs++) {
        int rr = (rs >> 1) * 16 + (rs & 1) * 8 + g;
        float m = sred[rr][0];
        #pragma unroll
        for (int ww = 1; ww < 8; ww++) m = fmaxf(m, sred[rr][ww]);
        rmx[rs] = m;
    }
    __syncthreads();
    float rsum[4];
    #pragma unroll
    for (int rs = 0; rs < 4; rs++) {
        int mt = rs >> 1, hh = (rs & 1) * 2;
        float s = 0.f;
        #pragma unroll
        for (int nt = 0; nt < 4; nt++) {
            float e0 = __expf(acc[mt][nt][hh]     - rmx[rs]);
            float e1 = __expf(acc[mt][nt][hh + 1] - rmx[rs]);
            acc[mt][nt][hh]     = e0;
            acc[mt][nt][hh + 1] = e1;
            s += e0 + e1;
        }
        s += __shfl_xor_sync(0xffffffffu, s, 1);
        s += __shfl_xor_sync(0xffffffffu, s, 2);
        rsum[rs] = s;
        if (tig == 0) sred[mt * 16 + (rs & 1) * 8 + g][w] = s;
    }
    __syncthreads();
    #pragma unroll
    for (int rs = 0; rs < 4; rs++) {
        int rr = (rs >> 1) * 16 + (rs & 1) * 8 + g;
        float s = sred[rr][0];
        #pragma unroll
        for (int ww = 1; ww < 8; ww++) s += sred[rr][ww];
        rsum[rs] = 1.0f / s;
    }

    __half* Pz = P + (long long)z * T_ * T_;
    #pragma unroll
    for (int mt = 0; mt < 2; mt++)
        #pragma unroll
        for (int nt = 0; nt < 4; nt++) {
            int col = wn + nt * 8 + 2 * tig;
            int r0 = bm + mt * 16 + g;
            float i0 = rsum[mt * 2 + 0], i1 = rsum[mt * 2 + 1];
            st_perm_h2(Pz + (long long)r0 * T_, col,
                       acc[mt][nt][0] * i0, acc[mt][nt][1] * i0);
            st_perm_h2(Pz + (long long)(r0 + 8) * T_, col,
                       acc[mt][nt][2] * i1, acc[mt][nt][3] * i1);
        }
}

// ======================================================================
// PV fp16: O = P @ V. Fully unrolled K loop (4 tiles).
// ======================================================================
__global__ void __launch_bounds__(256, 2) pv_kernel(
    const __half* __restrict__ Ph, const __half* __restrict__ vT, __half* __restrict__ O)
{
    extern __shared__ char smc[];
    char* sA = smc;
    char* sB = smc + NSTG * ABYT;

    int z = blockIdx.z, b = z >> 3, h = z & 7;
    int tid = threadIdx.x, w = tid >> 5, lane = tid & 31;
    int g = lane >> 2, tig = lane & 3;
    int bm = blockIdx.y * 128;
    int wm = (w & 3) * 32, wn = (w >> 2) * 32;

    unsigned uA = (unsigned)__cvta_generic_to_shared(sA);
    unsigned uB = (unsigned)__cvta_generic_to_shared(sB);
    int crow = tid >> 3, cch = tid & 7;
    unsigned cxor = (unsigned)((cch * 16) ^ ((crow & 1) << 6));

    const __half* aP[4]; const __half* bP[2];
    unsigned dA[4], dB[2];
    #pragma unroll
    for (int i = 0; i < 4; i++) {
        aP[i] = Ph + ((long long)z * T_ + bm + crow + i * 32) * T_ + cch * 8;
        dA[i] = uA + (unsigned)((crow + i * 32) * 128) + cxor;
    }
    #pragma unroll
    for (int i = 0; i < 2; i++) {
        bP[i] = vT + (long long)(h * DK_ + crow + i * 32) * (B_ * T_) + b * T_ + cch * 8;
        dB[i] = uB + (unsigned)((crow + i * 32) * 128) + cxor;
    }

    FRAG_OFFSETS()

    float acc[2][4][4];
    #pragma unroll
    for (int i = 0; i < 2; i++)
        #pragma unroll
        for (int j = 0; j < 4; j++)
            #pragma unroll
            for (int q = 0; q < 4; q++) acc[i][j][q] = 0.f;

    #pragma unroll
    for (int s = 0; s < 3; s++) {
        #pragma unroll
        for (int i = 0; i < 4; i++) CP16(dA[i] + (unsigned)(s * ABYT), aP[i] + s * 64);
        #pragma unroll
        for (int i = 0; i < 2; i++) CP16(dB[i] + (unsigned)(s * BBYT), bP[i] + s * 64);
        CPCOMMIT();
    }

    const int NKT = T_ / 64;   // 4
    #pragma unroll
    for (int kt = 0; kt < NKT; kt++) {
        CPWAIT(2);
        __syncthreads();
        int s = kt & 3;
        char* pA = sA + s * ABYT;
        char* pB = sB + s * BBYT;
        if (kt + 3 < NKT) {
            int rs = (kt + 3) & 3;
            int ko = (kt + 3) * 64;
            #pragma unroll
            for (int i = 0; i < 4; i++) CP16(dA[i] + (unsigned)(rs * ABYT), aP[i] + ko);
            #pragma unroll
            for (int i = 0; i < 2; i++) CP16(dB[i] + (unsigned)(rs * BBYT), bP[i] + ko);
        }
        CPCOMMIT();
        MMA_SUB2(pA, pB, paL, pbL)
        MMA_SUB2(pA, pB, paH, pbH)
    }

    #pragma unroll
    for (int mt = 0; mt < 2; mt++)
        #pragma unroll
        for (int nt = 0; nt < 4; nt++) {
            int gr   = b * T_ + bm + wm + mt * 16 + g;
            int colg = h * DK_ + wn + nt * 8 + 2 * tig;
            st_perm_h2(O + (long long)gr * D_, colg, acc[mt][nt][0], acc[mt][nt][1]);
            st_perm_h2(O + (long long)(gr + 8) * D_, colg, acc[mt][nt][2], acc[mt][nt][3]);
        }
}

// ---------------- PVAM head: 5 query positions per block ----------------
__global__ void __launch_bounds__(256) pvam_kernel(
    const float* __restrict__ wf, const float* __restrict__ emb,
    const int* __restrict__ gwp, const float* __restrict__ fc1,
    float* __restrict__ out)
{
    __shared__ float s_wp[5][D_];
    __shared__ float s_f[D_];
    __shared__ float s_sc[5][T_];
    __shared__ float s_red[40];
    int mg = blockIdx.x * 5, b = blockIdx.y;
    int tid = threadIdx.x;
    for (int i = tid; i < 5 * D_; i += 256) {
        int j = i >> 9, c = i & (D_ - 1);
        s_wp[j][c] = emb[(long long)gwp[mg + j] * D_ + c];
    }
    for (int i = tid; i < D_; i += 256) s_f[i] = fc1[i];
    __syncthreads();

    const float* wr = wf + ((long long)b * T_ + tid) * D_;
    float sc[5] = {0.f, 0.f, 0.f, 0.f, 0.f};
    for (int c4 = 0; c4 < D_ / 4; c4++) {
        float4 wv = *reinterpret_cast<const float4*>(&wr[c4 * 4]);
        float4 fv = *reinterpret_cast<const float4*>(&s_f[c4 * 4]);
        #pragma unroll
        for (int j = 0; j < 5; j++) {
            float4 pv = *reinterpret_cast<const float4*>(&s_wp[j][c4 * 4]);
            sc[j] += tanh_fast(wv.x + pv.x) * fv.x;
            sc[j] += tanh_fast(wv.y + pv.y) * fv.y;
            sc[j] += tanh_fast(wv.z + pv.z) * fv.z;
            sc[j] += tanh_fast(wv.w + pv.w) * fv.w;
        }
    }

    int wid = tid >> 5, lane = tid & 31;
    #pragma unroll
    for (int j = 0; j < 5; j++) {
        float mv = sc[j];
        #pragma unroll
        for (int o = 16; o; o >>= 1) mv = fmaxf(mv, __shfl_xor_sync(0xffffffffu, mv, o));
        if (lane == 0) s_red[wid] = mv;
        __syncthreads();
        if (tid < 32) {
            float t = (tid < 8) ? s_red[tid] : -3.0e38f;
            #pragma unroll
            for (int o = 4; o; o >>= 1) t = fmaxf(t, __shfl_xor_sync(0xffffffffu, t, o));
            if (tid == 0) s_red[32] = t;
        }
        __syncthreads();
        float e = __expf(sc[j] - s_red[32]);
        float sv = e;
        #pragma unroll
        for (int o = 16; o; o >>= 1) sv += __shfl_xor_sync(0xffffffffu, sv, o);
        if (lane == 0) s_red[8 + wid] = sv;
        __syncthreads();
        if (tid < 32) {
            float t = (tid < 8) ? s_red[8 + tid] : 0.f;
            #pragma unroll
            for (int o = 4; o; o >>= 1) t += __shfl_xor_sync(0xffffffffu, t, o);
            if (tid == 0) s_red[33] = t;
        }
        __syncthreads();
        s_sc[j][tid] = e * (1.0f / s_red[33]);
        __syncthreads();
    }

    const float* base = wf + (long long)b * T_ * D_;
    int c0 = tid, c1 = tid + 256;
    float a0[5] = {0.f, 0.f, 0.f, 0.f, 0.f};
    float a1[5] = {0.f, 0.f, 0.f, 0.f, 0.f};
    #pragma unroll 4
    for (int t = 0; t < T_; t++) {
        float w0 = base[(long long)t * D_ + c0];
        float w1 = base[(long long)t * D_ + c1];
        #pragma unroll
        for (int j = 0; j < 5; j++) {
            float s = s_sc[j][t];
            a0[j] += s * w0;
            a1[j] += s * w1;
        }
    }
    #pragma unroll
    for (int j = 0; j < 5; j++) {
        long long ob = ((long long)b * ML_ + mg + j) * D_;
        out[ob + c0] = a0[j];
        out[ob + c1] = a1[j];
    }
}

// ---------------- host launcher ----------------
extern "C" void kernel_launch(void* const* d_in, const int* in_sizes, int n_in,
                              void* d_out, int out_size)
{
    const float* x    = (const float*)d_in[0];
    const int*   ewp  = (const int*)  d_in[1];
    const int*   gwp  = (const int*)  d_in[2];
    const float* pos  = (const float*)d_in[3];
    const float* ln1s = (const float*)d_in[4];
    const float* ln1b = (const float*)d_in[5];
    const float* Wq   = (const float*)d_in[6];
    const float* bq   = (const float*)d_in[7];
    const float* Wk   = (const float*)d_in[8];
    const float* bk   = (const float*)d_in[9];
    const float* Wv   = (const float*)d_in[10];
    const float* bv   = (const float*)d_in[11];
    const float* Wo   = (const float*)d_in[12];
    const float* bo   = (const float*)d_in[13];
    const float* ln2s = (const float*)d_in[14];
    const float* ln2b = (const float*)d_in[15];
    const float* W1   = (const float*)d_in[16];
    const float* b1   = (const float*)d_in[17];
    const float* W2   = (const float*)d_in[18];
    const float* b2   = (const float*)d_in[19];
    const float* lnfs = (const float*)d_in[20];
    const float* lnfb = (const float*)d_in[21];
    const float* fc0w = (const float*)d_in[22];
    const float* fc0b = (const float*)d_in[23];
    const float* emb  = (const float*)d_in[24];
    const float* fc1  = (const float*)d_in[25];

    static float *enc = nullptr, *tmp, *q, *k, *v, *o, *p, *wT;
    if (!enc) {
        cudaGetSymbolAddress((void**)&enc, g_enc);
        cudaGetSymbolAddress((void**)&tmp, g_tmp);
        cudaGetSymbolAddress((void**)&q,   g_q);
        cudaGetSymbolAddress((void**)&k,   g_k);
        cudaGetSymbolAddress((void**)&v,   g_v);
        cudaGetSymbolAddress((void**)&o,   g_o);
        cudaGetSymbolAddress((void**)&p,   g_p);
        cudaGetSymbolAddress((void**)&wT,  g_wT);
        cudaFuncSetAttribute(tgemm_kernel,
                             cudaFuncAttributeMaxDynamicSharedMemorySize, TG_SMEM);
        cudaFuncSetAttribute(pv_kernel,
                             cudaFuncAttributeMaxDynamicSharedMemorySize, TG_SMEM);
    }

    __half* tmp_h = (__half*)tmp;
    __half* q_h   = (__half*)q;
    __half* k_h   = (__half*)k;
    __half* v_h   = (__half*)v;
    __half* o_h   = (__half*)o;
    __half* p_h   = (__half*)p;
    __half* wT_h  = (__half*)wT;

    const long long DD = (long long)D_ * D_;

    WP wp;
    wp.w[0]  = Wq;       wp.w[1]  = Wk;       wp.w[2]  = Wv;
    wp.w[3]  = Wo;       wp.w[4]  = W1;       wp.w[5]  = W2;
    wp.w[6]  = Wq + DD;  wp.w[7]  = Wk + DD;  wp.w[8]  = Wv + DD;
    wp.w[9]  = Wo + DD;  wp.w[10] = W1 + DD;  wp.w[11] = W2 + DD;
    wp.w[12] = fc0w;
    wtrans_kernel<<<dim3(16, 16, NWMAT), dim3(32, 8)>>>(wp, wT_h);

    prep_kernel<<<dim3(D_ / 32, T_ / 32, B_), dim3(32, 8)>>>(x, pos, ewp, enc);

    const int MT = B_ * T_;   // 8192

    for (int l = 0; l < L_; l++) {
        int vo = l * D_;
        const __half* wq = wT_h + (l * 6 + 0) * DD;
        const __half* wk = wT_h + (l * 6 + 1) * DD;
        const __half* wv = wT_h + (l * 6 + 2) * DD;
        const __half* wo = wT_h + (l * 6 + 3) * DD;
        const __half* w1 = wT_h + (l * 6 + 4) * DD;
        const __half* w2 = wT_h + (l * 6 + 5) * DD;

        ln_kernel<<<MT / 8, dim3(32, 8)>>>(enc, tmp_h, ln1s + vo, ln1b + vo);

        TGArgs aqkv;
        aqkv.t[0] = {tmp_h, wq, q_h, bq + vo, nullptr, 2, D_, 3};
        aqkv.t[1] = {tmp_h, wk, k_h, bk + vo, nullptr, 2, D_, 3};
        aqkv.t[2] = {wv, tmp_h, v_h, bv + vo, nullptr, 2 | 4, MT, 7};
        tgemm_kernel<<<dim3(512, 1, 3), 256, TG_SMEM>>>(aqkv);

        qk_softmax_kernel<<<dim3(T_ / 32, 1, B_ * NH_), 256>>>(q_h, k_h, p_h);
        pv_kernel<<<dim3(1, T_ / 128, B_ * NH_), 256, TG_SMEM>>>(p_h, v_h, o_h);

        TGArgs ao; ao.t[0] = {o_h, wo, enc, bo + vo, enc, 0, D_, 3};
        tgemm_kernel<<<dim3(512, 1, 1), 256, TG_SMEM>>>(ao);

        ln_kernel<<<MT / 8, dim3(32, 8)>>>(enc, tmp_h, ln2s + vo, ln2b + vo);
        TGArgs a1; a1.t[0] = {tmp_h, w1, o_h, b1 + vo, nullptr, 3, D_, 3};
        tgemm_kernel<<<dim3(512, 1, 1), 256, TG_SMEM>>>(a1);
        TGArgs a2; a2.t[0] = {o_h, w2, enc, b2 + vo, enc, 0, D_, 3};
        tgemm_kernel<<<dim3(512, 1, 1), 256, TG_SMEM>>>(a2);
    }

    ln_kernel<<<MT / 8, dim3(32, 8)>>>(enc, tmp_h, lnfs, lnfb);
    TGArgs af; af.t[0] = {tmp_h, wT_h + 12 * DD, q, fc0b, nullptr, 0, D_, 3};
    tgemm_kernel<<<dim3(512, 1, 1), 256, TG_SMEM>>>(af);

    pvam_kernel<<<dim3(ML_ / 5, B_), 256>>>(q, emb, gwp, fc1, (float*)d_out);
}

// round 11
// speedup vs baseline: 2.3213x; 1.0324x over previous
#include <cuda_runtime.h>
#include <cuda_fp16.h>
#include <math.h>

// ---------------- problem constants ----------------
#define B_  32
#define T_  256
#define D_  512
#define NH_ 8
#define DK_ 64
#define L_  2
#define ML_ 25
#define NWMAT 13

// ---------------- scratch ----------------
__device__ float g_enc[B_*T_*D_];
__device__ float g_tmp[B_*T_*D_];
__device__ float g_q  [B_*T_*D_];
__device__ float g_k  [B_*T_*D_];
__device__ float g_v  [B_*T_*D_];   // V^T halves [512, 8192]
__device__ float g_o  [B_*T_*D_];
__device__ float g_p  [B_*NH_*T_*T_];  // P halves, pitch 256
__device__ float g_wT [NWMAT*D_*D_];   // halves, perm layout

__device__ __forceinline__ float tanh_fast(float x) {
    float y;
    asm("tanh.approx.f32 %0, %1;" : "=f"(y) : "f"(x));
    return y;
}
__device__ __forceinline__ int pidx32(int k) {
    return ((k & 6) >> 1) * 8 + ((k >> 4) & 1) * 4 + ((k >> 3) & 1) * 2 + (k & 1);
}
__device__ __forceinline__ void st_perm_h2(__half* rowp, int c, float v0, float v1) {
    *reinterpret_cast<__half2*>(&rowp[(c & ~31) + pidx32(c & 31)]) = __floats2half2_rn(v0, v1);
}

#define CP16(dst, src) \
    asm volatile("cp.async.cg.shared.global [%0], [%1], 16;" :: "r"(dst), "l"(src) : "memory")
#define CPCOMMIT() asm volatile("cp.async.commit_group;" ::: "memory")
#define CPWAIT(n)  asm volatile("cp.async.wait_group %0;" :: "n"(n) : "memory")

__device__ __forceinline__ void mma_f16(float c[4],
                                        unsigned a0, unsigned a1, unsigned a2, unsigned a3,
                                        unsigned b0, unsigned b1)
{
    asm volatile(
        "mma.sync.aligned.m16n8k16.row.col.f32.f16.f16.f32 "
        "{%0,%1,%2,%3}, {%4,%5,%6,%7}, {%8,%9}, {%0,%1,%2,%3};"
        : "+f"(c[0]), "+f"(c[1]), "+f"(c[2]), "+f"(c[3])
        : "r"(a0), "r"(a1), "r"(a2), "r"(a3), "r"(b0), "r"(b1));
}

// ---------------- tiling ----------------
#define ABYT 16384
#define BBYT 8192
#define NSTG3 3
#define TG_SMEM3 (NSTG3 * (ABYT + BBYT))   // 73728

// ===== wide warp tile (64x32) fragment machinery, 4 warps / 128 threads =====
#define FRAG_OFFSETS_W()                                                              \
    unsigned paL[8], pbL[4];                                                          \
    _Pragma("unroll")                                                                 \
    for (int r2 = 0; r2 < 8; r2++) {                                                  \
        int row = wm + r2 * 8 + g;                                                    \
        paL[r2] = (unsigned)(row * 128 + tig * 16 + ((row & 1) << 6));                \
    }                                                                                 \
    _Pragma("unroll")                                                                 \
    for (int r2 = 0; r2 < 4; r2++) {                                                  \
        int rob = wn + r2 * 8 + g;                                                    \
        pbL[r2] = (unsigned)(rob * 128 + tig * 16 + ((rob & 1) << 6));                \
    }

#define MMA_SUB_W(stgA, stgB, XORV) {                                                 \
    uint4 aU[8], bU[4];                                                               \
    _Pragma("unroll")                                                                 \
    for (int r2 = 0; r2 < 8; r2++)                                                    \
        aU[r2] = *reinterpret_cast<const uint4*>((stgA) + (paL[r2] ^ (XORV)));        \
    _Pragma("unroll")                                                                 \
    for (int r2 = 0; r2 < 4; r2++)                                                    \
        bU[r2] = *reinterpret_cast<const uint4*>((stgB) + (pbL[r2] ^ (XORV)));        \
    _Pragma("unroll")                                                                 \
    for (int mt = 0; mt < 4; mt++)                                                    \
        _Pragma("unroll")                                                             \
        for (int nt = 0; nt < 4; nt++) {                                              \
            mma_f16(acc[mt][nt], aU[2*mt].x, aU[2*mt+1].x, aU[2*mt].y, aU[2*mt+1].y,  \
                    bU[nt].x, bU[nt].y);                                              \
            mma_f16(acc[mt][nt], aU[2*mt].z, aU[2*mt+1].z, aU[2*mt].w, aU[2*mt+1].w,  \
                    bU[nt].z, bU[nt].w);                                              \
        }                                                                             \
}

// ===== narrow (32x32) machinery for qk_softmax (8 warps / 256 threads) =====
#define FRAG_OFFSETS()                                                                \
    unsigned qaL[4], qaH[4], qbL[4], qbH[4];                                          \
    _Pragma("unroll")                                                                 \
    for (int r2 = 0; r2 < 4; r2++) {                                                  \
        int row = wm + r2 * 8 + g;                                                    \
        qaL[r2] = (unsigned)(row * 128 + tig * 16 + ((row & 1) << 6));                \
        qaH[r2] = qaL[r2] ^ 64u;                                                      \
        int rob = wn + r2 * 8 + g;                                                    \
        qbL[r2] = (unsigned)(rob * 128 + tig * 16 + ((rob & 1) << 6));                \
        qbH[r2] = qbL[r2] ^ 64u;                                                      \
    }

#define MMA_SUB2(stgA, stgB, AOFF, BOFF) {                                            \
    uint4 aU[4], bU[4];                                                               \
    _Pragma("unroll")                                                                 \
    for (int r2 = 0; r2 < 4; r2++) {                                                  \
        aU[r2] = *reinterpret_cast<const uint4*>((stgA) + (AOFF)[r2]);                \
        bU[r2] = *reinterpret_cast<const uint4*>((stgB) + (BOFF)[r2]);                \
    }                                                                                 \
    _Pragma("unroll")                                                                 \
    for (int mt = 0; mt < 2; mt++)                                                    \
        _Pragma("unroll")                                                             \
        for (int nt = 0; nt < 4; nt++) {                                              \
            mma_f16(acc[mt][nt], aU[2*mt].x, aU[2*mt+1].x, aU[2*mt].y, aU[2*mt+1].y,  \
                    bU[nt].x, bU[nt].y);                                              \
            mma_f16(acc[mt][nt], aU[2*mt].z, aU[2*mt+1].z, aU[2*mt].w, aU[2*mt+1].w,  \
                    bU[nt].z, bU[nt].w);                                              \
        }                                                                             \
}

// ---------------- prep ----------------
__global__ void prep_kernel(const float* __restrict__ x, const float* __restrict__ pos,
                            const int* __restrict__ ewp, float* __restrict__ enc)
{
    __shared__ float tile[32][33];
    int b  = blockIdx.z;
    int d0 = blockIdx.x * 32, t0 = blockIdx.y * 32;
    int tx = threadIdx.x, ty = threadIdx.y;
    const float* xb = x + (long long)b * D_ * T_;
    #pragma unroll
    for (int i = 0; i < 4; i++) {
        int d = ty + i * 8;
        tile[d][tx] = xb[(long long)(d0 + d) * T_ + t0 + tx];
    }
    __syncthreads();
    #pragma unroll
    for (int i = 0; i < 4; i++) {
        int tl = ty + i * 8;
        int t = t0 + tl, d = d0 + tx;
        int pr = ewp[t];
        enc[(((long long)b * T_) + t) * D_ + d] =
            tile[tx][tl] * 22.62741699796952f + pos[(long long)pr * D_ + d];
    }
}

// ---------------- weight transpose -> half perm ----------------
struct WP { const float* w[NWMAT]; };
__global__ void wtrans_kernel(WP p, __half* __restrict__ out)
{
    __shared__ float t[32][33];
    int mi = blockIdx.z;
    const float* W = p.w[mi];
    __half* O = out + (long long)mi * D_ * D_;
    int n0 = blockIdx.x * 32, k0 = blockIdx.y * 32;
    int tx = threadIdx.x, ty = threadIdx.y;
    #pragma unroll
    for (int i = 0; i < 4; i++) {
        int k = k0 + ty + i * 8;
        t[ty + i * 8][tx] = W[(long long)k * D_ + n0 + tx];
    }
    __syncthreads();
    #pragma unroll
    for (int i = 0; i < 4; i++) {
        int n = n0 + ty + i * 8;
        O[(long long)n * D_ + k0 + pidx32(tx)] = __float2half(t[tx][ty + i * 8]);
    }
}

// ---------------- layernorm -> half perm ----------------
__global__ void ln_kernel(const float* __restrict__ in, __half* __restrict__ out,
                          const float* __restrict__ gs, const float* __restrict__ gb)
{
    int row  = blockIdx.x * 8 + threadIdx.y;
    int lane = threadIdx.x;
    const float* r = in + (long long)row * D_;
    float4 xv[4];
    #pragma unroll
    for (int j = 0; j < 4; j++)
        xv[j] = *reinterpret_cast<const float4*>(&r[(j * 32 + lane) * 4]);
    float s = 0.f;
    #pragma unroll
    for (int j = 0; j < 4; j++) s += xv[j].x + xv[j].y + xv[j].z + xv[j].w;
    #pragma unroll
    for (int o = 16; o; o >>= 1) s += __shfl_xor_sync(0xffffffffu, s, o);
    float mean = s * (1.0f / D_);
    float vs = 0.f;
    #pragma unroll
    for (int j = 0; j < 4; j++) {
        float a = xv[j].x - mean, b2 = xv[j].y - mean, c = xv[j].z - mean, d = xv[j].w - mean;
        vs += a * a + b2 * b2 + c * c + d * d;
    }
    #pragma unroll
    for (int o = 16; o; o >>= 1) vs += __shfl_xor_sync(0xffffffffu, vs, o);
    float rstd = rsqrtf(vs * (1.0f / D_) + 1e-5f);
    __half* w = out + (long long)row * D_;
    #pragma unroll
    for (int j = 0; j < 4; j++) {
        int c0 = (j * 32 + lane) * 4;
        float4 sv = *reinterpret_cast<const float4*>(&gs[c0]);
        float4 bv = *reinterpret_cast<const float4*>(&gb[c0]);
        float tx = (xv[j].x - mean) * rstd * sv.x + bv.x;
        float ty = (xv[j].y - mean) * rstd * sv.y + bv.y;
        float tz = (xv[j].z - mean) * rstd * sv.z + bv.z;
        float tw = (xv[j].w - mean) * rstd * sv.w + bv.w;
        st_perm_h2(w, c0,     tx, ty);
        st_perm_h2(w, c0 + 2, tz, tw);
    }
}

// ======================================================================
// fp16 MMA GEMM: 128-thread CTA, 4 warps of 64x32. 3-stage cp.async.
// ======================================================================
struct TGB { const __half* A; const __half* Bt; void* C; const float* bias;
             const float* resid; int flags; int ldc; int bxShift; };
struct TGArgs { TGB t[3]; };

__global__ void __launch_bounds__(128, 3) tgemm_kernel(TGArgs args)
{
    extern __shared__ char smc[];
    char* sA = smc;
    char* sB = smc + NSTG3 * ABYT;
    TGB tb = args.t[blockIdx.z];

    int tid = threadIdx.x, w = tid >> 5, lane = tid & 31;
    int g = lane >> 2, tig = lane & 3;
    int bx = blockIdx.x;
    int bn = (bx & ((1 << tb.bxShift) - 1)) * 64;
    int bm = (bx >> tb.bxShift) * 128;
    int wm = (w & 1) * 64, wn = (w >> 1) * 32;

    unsigned uA = (unsigned)__cvta_generic_to_shared(sA);
    unsigned uB = (unsigned)__cvta_generic_to_shared(sB);
    int crow = tid >> 3, cch = tid & 7;                 // crow 0..15
    unsigned cxor = (unsigned)((cch * 16) ^ ((crow & 1) << 6));
    unsigned aBase = uA + (unsigned)(crow * 128) + cxor;
    unsigned bBase = uB + (unsigned)(crow * 128) + cxor;
    const __half* aSrc = tb.A  + (long long)(bm + crow) * D_ + cch * 8;
    const __half* bSrc = tb.Bt + (long long)(bn + crow) * D_ + cch * 8;

    FRAG_OFFSETS_W()

    float acc[4][4][4];
    #pragma unroll
    for (int i = 0; i < 4; i++)
        #pragma unroll
        for (int j = 0; j < 4; j++)
            #pragma unroll
            for (int q = 0; q < 4; q++) acc[i][j][q] = 0.f;

    #pragma unroll
    for (int s = 0; s < 2; s++) {
        #pragma unroll
        for (int i = 0; i < 8; i++)
            CP16(aBase + (unsigned)(s * ABYT + i * 2048), aSrc + i * 16 * D_ + s * 64);
        #pragma unroll
        for (int i = 0; i < 4; i++)
            CP16(bBase + (unsigned)(s * BBYT + i * 2048), bSrc + i * 16 * D_ + s * 64);
        CPCOMMIT();
    }

    const int NKT = D_ / 64;   // 8
    #pragma unroll
    for (int kt = 0; kt < NKT; kt++) {
        CPWAIT(1);
        __syncthreads();
        int s = kt % NSTG3;
        char* pA = sA + s * ABYT;
        char* pB = sB + s * BBYT;
        if (kt + 2 < NKT) {
            int rs = (kt + 2) % NSTG3;
            int ko = (kt + 2) * 64;
            #pragma unroll
            for (int i = 0; i < 8; i++)
                CP16(aBase + (unsigned)(rs * ABYT + i * 2048), aSrc + i * 16 * D_ + ko);
            #pragma unroll
            for (int i = 0; i < 4; i++)
                CP16(bBase + (unsigned)(rs * BBYT + i * 2048), bSrc + i * 16 * D_ + ko);
        }
        CPCOMMIT();
        MMA_SUB_W(pA, pB, 0u)
        MMA_SUB_W(pA, pB, 64u)
    }

    int flags = tb.flags, ldc = tb.ldc;
    #pragma unroll
    for (int mt = 0; mt < 4; mt++) {
        #pragma unroll
        for (int nt = 0; nt < 4; nt++) {
            int row0 = bm + wm + mt * 16 + g;
            int col  = bn + wn + nt * 8 + 2 * tig;
            float v00 = acc[mt][nt][0], v01 = acc[mt][nt][1];
            float v10 = acc[mt][nt][2], v11 = acc[mt][nt][3];
            if (flags & 4) {
                float b0 = tb.bias[row0], b1 = tb.bias[row0 + 8];
                v00 += b0; v01 += b0; v10 += b1; v11 += b1;
            } else {
                float2 bv = *reinterpret_cast<const float2*>(&tb.bias[col]);
                v00 += bv.x; v01 += bv.y; v10 += bv.x; v11 += bv.y;
            }
            if (flags & 1) {
                v00 = fmaxf(v00, 0.f); v01 = fmaxf(v01, 0.f);
                v10 = fmaxf(v10, 0.f); v11 = fmaxf(v11, 0.f);
            }
            if (tb.resid) {
                float2 r0 = *reinterpret_cast<const float2*>(
                    &tb.resid[(long long)row0 * ldc + col]);
                float2 r1 = *reinterpret_cast<const float2*>(
                    &tb.resid[(long long)(row0 + 8) * ldc + col]);
                v00 += r0.x; v01 += r0.y; v10 += r1.x; v11 += r1.y;
            }
            if (flags & 2) {
                __half* r0p = (__half*)tb.C + (long long)row0 * ldc;
                __half* r1p = (__half*)tb.C + (long long)(row0 + 8) * ldc;
                st_perm_h2(r0p, col, v00, v01);
                st_perm_h2(r1p, col, v10, v11);
            } else {
                float* Cf = (float*)tb.C;
                *reinterpret_cast<float2*>(&Cf[(long long)row0 * ldc + col]) =
                    make_float2(v00, v01);
                *reinterpret_cast<float2*>(&Cf[(long long)(row0 + 8) * ldc + col]) =
                    make_float2(v10, v11);
            }
        }
    }
}

// ======================================================================
// Fused QK^T + softmax: 256 threads, CTA = 32 q-rows x 256 key cols.
// ======================================================================
__global__ void __launch_bounds__(256, 2) qk_softmax_kernel(
    const __half* __restrict__ q, const __half* __restrict__ k, __half* __restrict__ P)
{
    __shared__ __align__(16) char sA[4096];
    __shared__ __align__(16) char sB[32768];
    __shared__ float sred[32][8];

    int z = blockIdx.z, b = z >> 3, h = z & 7;
    int bm = blockIdx.x * 32;
    int tid = threadIdx.x, w = tid >> 5, lane = tid & 31;
    int g = lane >> 2, tig = lane & 3;
    int wm = 0, wn = w * 32;

    unsigned uA = (unsigned)__cvta_generic_to_shared(sA);
    unsigned uB = (unsigned)__cvta_generic_to_shared(sB);

    {
        int row = tid >> 3, ch = tid & 7;
        unsigned cx = (unsigned)((ch * 16) ^ ((row & 1) << 6));
        CP16(uA + (unsigned)(row * 128) + cx,
             q + (long long)(b * T_ + bm + row) * D_ + h * DK_ + ch * 8);
        #pragma unroll
        for (int i = 0; i < 8; i++) {
            int idx = tid + i * 256;
            int br = idx >> 3, bch = idx & 7;
            unsigned bx2 = (unsigned)((bch * 16) ^ ((br & 1) << 6));
            CP16(uB + (unsigned)(br * 128) + bx2,
                 k + (long long)(b * T_ + br) * D_ + h * DK_ + bch * 8);
        }
    }
    CPCOMMIT();

    FRAG_OFFSETS()

    float acc[2][4][4];
    #pragma unroll
    for (int i = 0; i < 2; i++)
        #pragma unroll
        for (int j = 0; j < 4; j++)
            #pragma unroll
            for (int qq = 0; qq < 4; qq++) acc[i][j][qq] = 0.f;

    CPWAIT(0);
    __syncthreads();
    MMA_SUB2(sA, sB, qaL, qbL)
    MMA_SUB2(sA, sB, qaH, qbH)

    #pragma unroll
    for (int i = 0; i < 2; i++)
        #pragma unroll
        for (int j = 0; j < 4; j++)
            #pragma unroll
            for (int qq = 0; qq < 4; qq++) acc[i][j][qq] *= 0.125f;

    float rmx[4];
    #pragma unroll
    for (int rs = 0; rs < 4; rs++) {
        int mt = rs >> 1, hh = (rs & 1) * 2;
        float m = -3.0e38f;
        #pragma unroll
        for (int nt = 0; nt < 4; nt++)
            m = fmaxf(m, fmaxf(acc[mt][nt][hh], acc[mt][nt][hh + 1]));
        m = fmaxf(m, __shfl_xor_sync(0xffffffffu, m, 1));
        m = fmaxf(m, __shfl_xor_sync(0xffffffffu, m, 2));
        rmx[rs] = m;
        if (tig == 0) sred[mt * 16 + (rs & 1) * 8 + g][w] = m;
    }
    __syncthreads();
    #pragma unroll
    for (int rs = 0; rs < 4; rs++) {
        int rr = (rs >> 1) * 16 + (rs & 1) * 8 + g;
        float m = sred[rr][0];
        #pragma unroll
        for (int ww = 1; ww < 8; ww++) m = fmaxf(m, sred[rr][ww]);
        rmx[rs] = m;
    }
    __syncthreads();
    float rsum[4];
    #pragma unroll
    for (int rs = 0; rs < 4; rs++) {
        int mt = rs >> 1, hh = (rs & 1) * 2;
        float s = 0.f;
        #pragma unroll
        for (int nt = 0; nt < 4; nt++) {
            float e0 = __expf(acc[mt][nt][hh]     - rmx[rs]);
            float e1 = __expf(acc[mt][nt][hh + 1] - rmx[rs]);
            acc[mt][nt][hh]     = e0;
            acc[mt][nt][hh + 1] = e1;
            s += e0 + e1;
        }
        s += __shfl_xor_sync(0xffffffffu, s, 1);
        s += __shfl_xor_sync(0xffffffffu, s, 2);
        rsum[rs] = s;
        if (tig == 0) sred[mt * 16 + (rs & 1) * 8 + g][w] = s;
    }
    __syncthreads();
    #pragma unroll
    for (int rs = 0; rs < 4; rs++) {
        int rr = (rs >> 1) * 16 + (rs & 1) * 8 + g;
        float s = sred[rr][0];
        #pragma unroll
        for (int ww = 1; ww < 8; ww++) s += sred[rr][ww];
        rsum[rs] = 1.0f / s;
    }

    __half* Pz = P + (long long)z * T_ * T_;
    #pragma unroll
    for (int mt = 0; mt < 2; mt++)
        #pragma unroll
        for (int nt = 0; nt < 4; nt++) {
            int col = wn + nt * 8 + 2 * tig;
            int r0 = bm + mt * 16 + g;
            float i0 = rsum[mt * 2 + 0], i1 = rsum[mt * 2 + 1];
            st_perm_h2(Pz + (long long)r0 * T_, col,
                       acc[mt][nt][0] * i0, acc[mt][nt][1] * i0);
            st_perm_h2(Pz + (long long)(r0 + 8) * T_, col,
                       acc[mt][nt][2] * i1, acc[mt][nt][3] * i1);
        }
}

// ======================================================================
// PV fp16: 128-thread CTA, 4 warps of 64x32, 3 stages. K = 256.
// ======================================================================
__global__ void __launch_bounds__(128, 3) pv_kernel(
    const __half* __restrict__ Ph, const __half* __restrict__ vT, __half* __restrict__ O)
{
    extern __shared__ char smc[];
    char* sA = smc;
    char* sB = smc + NSTG3 * ABYT;

    int z = blockIdx.z, b = z >> 3, h = z & 7;
    int tid = threadIdx.x, w = tid >> 5, lane = tid & 31;
    int g = lane >> 2, tig = lane & 3;
    int bm = blockIdx.y * 128;
    int wm = (w & 1) * 64, wn = (w >> 1) * 32;

    unsigned uA = (unsigned)__cvta_generic_to_shared(sA);
    unsigned uB = (unsigned)__cvta_generic_to_shared(sB);
    int crow = tid >> 3, cch = tid & 7;
    unsigned cxor = (unsigned)((cch * 16) ^ ((crow & 1) << 6));
    unsigned aBase = uA + (unsigned)(crow * 128) + cxor;
    unsigned bBase = uB + (unsigned)(crow * 128) + cxor;
    const __half* aSrc = Ph + ((long long)z * T_ + bm + crow) * T_ + cch * 8;
    const __half* bSrc = vT + (long long)(h * DK_ + crow) * (B_ * T_) + b * T_ + cch * 8;

    FRAG_OFFSETS_W()

    float acc[4][4][4];
    #pragma unroll
    for (int i = 0; i < 4; i++)
        #pragma unroll
        for (int j = 0; j < 4; j++)
            #pragma unroll
            for (int q = 0; q < 4; q++) acc[i][j][q] = 0.f;

    #pragma unroll
    for (int s = 0; s < 2; s++) {
        #pragma unroll
        for (int i = 0; i < 8; i++)
            CP16(aBase + (unsigned)(s * ABYT + i * 2048), aSrc + i * 16 * T_ + s * 64);
        #pragma unroll
        for (int i = 0; i < 4; i++)
            CP16(bBase + (unsigned)(s * BBYT + i * 2048), bSrc + i * 16 * (B_ * T_) + s * 64);
        CPCOMMIT();
    }

    const int NKT = T_ / 64;   // 4
    #pragma unroll
    for (int kt = 0; kt < NKT; kt++) {
        CPWAIT(1);
        __syncthreads();
        int s = kt % NSTG3;
        char* pA = sA + s * ABYT;
        char* pB = sB + s * BBYT;
        if (kt + 2 < NKT) {
            int rs = (kt + 2) % NSTG3;
            int ko = (kt + 2) * 64;
            #pragma unroll
            for (int i = 0; i < 8; i++)
                CP16(aBase + (unsigned)(rs * ABYT + i * 2048), aSrc + i * 16 * T_ + ko);
            #pragma unroll
            for (int i = 0; i < 4; i++)
                CP16(bBase + (unsigned)(rs * BBYT + i * 2048), bSrc + i * 16 * (B_ * T_) + ko);
        }
        CPCOMMIT();
        MMA_SUB_W(pA, pB, 0u)
        MMA_SUB_W(pA, pB, 64u)
    }

    #pragma unroll
    for (int mt = 0; mt < 4; mt++)
        #pragma unroll
        for (int nt = 0; nt < 4; nt++) {
            int gr   = b * T_ + bm + wm + mt * 16 + g;
            int colg = h * DK_ + wn + nt * 8 + 2 * tig;
            st_perm_h2(O + (long long)gr * D_, colg, acc[mt][nt][0], acc[mt][nt][1]);
            st_perm_h2(O + (long long)(gr + 8) * D_, colg, acc[mt][nt][2], acc[mt][nt][3]);
        }
}

// ---------------- PVAM head: 5 query positions per block ----------------
__global__ void __launch_bounds__(256) pvam_kernel(
    const float* __restrict__ wf, const float* __restrict__ emb,
    const int* __restrict__ gwp, const float* __restrict__ fc1,
    float* __restrict__ out)
{
    __shared__ float s_wp[5][D_];
    __shared__ float s_f[D_];
    __shared__ float s_sc[5][T_];
    __shared__ float s_red[40];
    int mg = blockIdx.x * 5, b = blockIdx.y;
    int tid = threadIdx.x;
    for (int i = tid; i < 5 * D_; i += 256) {
        int j = i >> 9, c = i & (D_ - 1);
        s_wp[j][c] = emb[(long long)gwp[mg + j] * D_ + c];
    }
    for (int i = tid; i < D_; i += 256) s_f[i] = fc1[i];
    __syncthreads();

    const float* wr = wf + ((long long)b * T_ + tid) * D_;
    float sc[5] = {0.f, 0.f, 0.f, 0.f, 0.f};
    for (int c4 = 0; c4 < D_ / 4; c4++) {
        float4 wv = *reinterpret_cast<const float4*>(&wr[c4 * 4]);
        float4 fv = *reinterpret_cast<const float4*>(&s_f[c4 * 4]);
        #pragma unroll
        for (int j = 0; j < 5; j++) {
            float4 pv = *reinterpret_cast<const float4*>(&s_wp[j][c4 * 4]);
            sc[j] += tanh_fast(wv.x + pv.x) * fv.x;
            sc[j] += tanh_fast(wv.y + pv.y) * fv.y;
            sc[j] += tanh_fast(wv.z + pv.z) * fv.z;
            sc[j] += tanh_fast(wv.w + pv.w) * fv.w;
        }
    }

    int wid = tid >> 5, lane = tid & 31;
    #pragma unroll
    for (int j = 0; j < 5; j++) {
        float mv = sc[j];
        #pragma unroll
        for (int o = 16; o; o >>= 1) mv = fmaxf(mv, __shfl_xor_sync(0xffffffffu, mv, o));
        if (lane == 0) s_red[wid] = mv;
        __syncthreads();
        if (tid < 32) {
            float t = (tid < 8) ? s_red[tid] : -3.0e38f;
            #pragma unroll
            for (int o = 4; o; o >>= 1) t = fmaxf(t, __shfl_xor_sync(0xffffffffu, t, o));
            if (tid == 0) s_red[32] = t;
        }
        __syncthreads();
        float e = __expf(sc[j] - s_red[32]);
        float sv = e;
        #pragma unroll
        for (int o = 16; o; o >>= 1) sv += __shfl_xor_sync(0xffffffffu, sv, o);
        if (lane == 0) s_red[8 + wid] = sv;
        __syncthreads();
        if (tid < 32) {
            float t = (tid < 8) ? s_red[8 + tid] : 0.f;
            #pragma unroll
            for (int o = 4; o; o >>= 1) t += __shfl_xor_sync(0xffffffffu, t, o);
            if (tid == 0) s_red[33] = t;
        }
        __syncthreads();
        s_sc[j][tid] = e * (1.0f / s_red[33]);
        __syncthreads();
    }

    const float* base = wf + (long long)b * T_ * D_;
    int c0 = tid, c1 = tid + 256;
    float a0[5] = {0.f, 0.f, 0.f, 0.f, 0.f};
    float a1[5] = {0.f, 0.f, 0.f, 0.f, 0.f};
    #pragma unroll 4
    for (int t = 0; t < T_; t++) {
        float w0 = base[(long long)t * D_ + c0];
        float w1 = base[(long long)t * D_ + c1];
        #pragma unroll
        for (int j = 0; j < 5; j++) {
            float s = s_sc[j][t];
            a0[j] += s * w0;
            a1[j] += s * w1;
        }
    }
    #pragma unroll
    for (int j = 0; j < 5; j++) {
        long long ob = ((long long)b * ML_ + mg + j) * D_;
        out[ob + c0] = a0[j];
        out[ob + c1] = a1[j];
    }
}

// ---------------- host launcher ----------------
extern "C" void kernel_launch(void* const* d_in, const int* in_sizes, int n_in,
                              void* d_out, int out_size)
{
    const float* x    = (const float*)d_in[0];
    const int*   ewp  = (const int*)  d_in[1];
    const int*   gwp  = (const int*)  d_in[2];
    const float* pos  = (const float*)d_in[3];
    const float* ln1s = (const float*)d_in[4];
    const float* ln1b = (const float*)d_in[5];
    const float* Wq   = (const float*)d_in[6];
    const float* bq   = (const float*)d_in[7];
    const float* Wk   = (const float*)d_in[8];
    const float* bk   = (const float*)d_in[9];
    const float* Wv   = (const float*)d_in[10];
    const float* bv   = (const float*)d_in[11];
    const float* Wo   = (const float*)d_in[12];
    const float* bo   = (const float*)d_in[13];
    const float* ln2s = (const float*)d_in[14];
    const float* ln2b = (const float*)d_in[15];
    const float* W1   = (const float*)d_in[16];
    const float* b1   = (const float*)d_in[17];
    const float* W2   = (const float*)d_in[18];
    const float* b2   = (const float*)d_in[19];
    const float* lnfs = (const float*)d_in[20];
    const float* lnfb = (const float*)d_in[21];
    const float* fc0w = (const float*)d_in[22];
    const float* fc0b = (const float*)d_in[23];
    const float* emb  = (const float*)d_in[24];
    const float* fc1  = (const float*)d_in[25];

    static float *enc = nullptr, *tmp, *q, *k, *v, *o, *p, *wT;
    if (!enc) {
        cudaGetSymbolAddress((void**)&enc, g_enc);
        cudaGetSymbolAddress((void**)&tmp, g_tmp);
        cudaGetSymbolAddress((void**)&q,   g_q);
        cudaGetSymbolAddress((void**)&k,   g_k);
        cudaGetSymbolAddress((void**)&v,   g_v);
        cudaGetSymbolAddress((void**)&o,   g_o);
        cudaGetSymbolAddress((void**)&p,   g_p);
        cudaGetSymbolAddress((void**)&wT,  g_wT);
        cudaFuncSetAttribute(tgemm_kernel,
                             cudaFuncAttributeMaxDynamicSharedMemorySize, TG_SMEM3);
        cudaFuncSetAttribute(pv_kernel,
                             cudaFuncAttributeMaxDynamicSharedMemorySize, TG_SMEM3);
    }

    __half* tmp_h = (__half*)tmp;
    __half* q_h   = (__half*)q;
    __half* k_h   = (__half*)k;
    __half* v_h   = (__half*)v;
    __half* o_h   = (__half*)o;
    __half* p_h   = (__half*)p;
    __half* wT_h  = (__half*)wT;

    const long long DD = (long long)D_ * D_;

    WP wp;
    wp.w[0]  = Wq;       wp.w[1]  = Wk;       wp.w[2]  = Wv;
    wp.w[3]  = Wo;       wp.w[4]  = W1;       wp.w[5]  = W2;
    wp.w[6]  = Wq + DD;  wp.w[7]  = Wk + DD;  wp.w[8]  = Wv + DD;
    wp.w[9]  = Wo + DD;  wp.w[10] = W1 + DD;  wp.w[11] = W2 + DD;
    wp.w[12] = fc0w;
    wtrans_kernel<<<dim3(16, 16, NWMAT), dim3(32, 8)>>>(wp, wT_h);

    prep_kernel<<<dim3(D_ / 32, T_ / 32, B_), dim3(32, 8)>>>(x, pos, ewp, enc);

    const int MT = B_ * T_;   // 8192

    for (int l = 0; l < L_; l++) {
        int vo = l * D_;
        const __half* wq = wT_h + (l * 6 + 0) * DD;
        const __half* wk = wT_h + (l * 6 + 1) * DD;
        const __half* wv = wT_h + (l * 6 + 2) * DD;
        const __half* wo = wT_h + (l * 6 + 3) * DD;
        const __half* w1 = wT_h + (l * 6 + 4) * DD;
        const __half* w2 = wT_h + (l * 6 + 5) * DD;

        ln_kernel<<<MT / 8, dim3(32, 8)>>>(enc, tmp_h, ln1s + vo, ln1b + vo);

        TGArgs aqkv;
        aqkv.t[0] = {tmp_h, wq, q_h, bq + vo, nullptr, 2, D_, 3};
        aqkv.t[1] = {tmp_h, wk, k_h, bk + vo, nullptr, 2, D_, 3};
        aqkv.t[2] = {wv, tmp_h, v_h, bv + vo, nullptr, 2 | 4, MT, 7};
        tgemm_kernel<<<dim3(512, 1, 3), 128, TG_SMEM3>>>(aqkv);

        qk_softmax_kernel<<<dim3(T_ / 32, 1, B_ * NH_), 256>>>(q_h, k_h, p_h);
        pv_kernel<<<dim3(1, T_ / 128, B_ * NH_), 128, TG_SMEM3>>>(p_h, v_h, o_h);

        TGArgs ao; ao.t[0] = {o_h, wo, enc, bo + vo, enc, 0, D_, 3};
        tgemm_kernel<<<dim3(512, 1, 1), 128, TG_SMEM3>>>(ao);

        ln_kernel<<<MT / 8, dim3(32, 8)>>>(enc, tmp_h, ln2s + vo, ln2b + vo);
        TGArgs a1; a1.t[0] = {tmp_h, w1, o_h, b1 + vo, nullptr, 3, D_, 3};
        tgemm_kernel<<<dim3(512, 1, 1), 128, TG_SMEM3>>>(a1);
        TGArgs a2; a2.t[0] = {o_h, w2, enc, b2 + vo, enc, 0, D_, 3};
        tgemm_kernel<<<dim3(512, 1, 1), 128, TG_SMEM3>>>(a2);
    }

    ln_kernel<<<MT / 8, dim3(32, 8)>>>(enc, tmp_h, lnfs, lnfb);
    TGArgs af; af.t[0] = {tmp_h, wT_h + 12 * DD, q, fc0b, nullptr, 0, D_, 3};
    tgemm_kernel<<<dim3(512, 1, 1), 128, TG_SMEM3>>>(af);

    pvam_kernel<<<dim3(ML_ / 5, B_), 256>>>(q, emb, gwp, fc1, (float*)d_out);
}